// round 1
// baseline (speedup 1.0000x reference)
#include <cuda_runtime.h>
#include <math.h>

// Problem constants (fixed by setup_inputs)
#define BB  8
#define LL  2048
#define HH  1024
#define DH  1024

// GEMM tiling
#define BM 128
#define BN 128
#define BK 16
#define TM 8
#define TN 8
#define NTHREADS 256

// Scratch (static device globals — allocation-free)
__device__ float g_Q[BB * LL * DH];            // 64 MB
__device__ float g_K[BB * LL * DH];            // 64 MB
__device__ float g_V[BB * LL * DH];            // 64 MB
__device__ float g_S[(size_t)BB * LL * LL];    // 128 MB

// Accurate-enough sincos that survives --use_fast_math:
// Cody-Waite reduce by 2*pi (theta in [0, ~2100)), then sincosf on |r|<=pi.
__device__ __forceinline__ void sincos_red(float theta, float* s, float* c) {
    const float INV_2PI = 0.15915494309189535f;
    const float PI2_HI  = 6.28318548202514648f;   // float(2*pi)
    const float PI2_LO  = -1.7484555e-7f;         // 2*pi - PI2_HI
    float k = nearbyintf(theta * INV_2PI);
    float r = __fmaf_rn(-k, PI2_HI, theta);
    r = __fmaf_rn(-k, PI2_LO, r);
    sincosf(r, s, c);
}

// XPOS_MODE: 0 = none, 1 = Q (scale), 2 = K (1/scale)
// TRANS_B:  false -> B is [K][N] row-major; true -> B is [N][K] row-major (C = A*B^T)
template<int XPOS_MODE, bool TRANS_B>
__global__ void gemm_kernel(const float* __restrict__ A,
                            const float* __restrict__ B,
                            float* __restrict__ C,
                            int M, int N, int K,
                            long long strideA, long long strideB, long long strideC)
{
    __shared__ __align__(16) float As[BK][BM + 4];
    __shared__ __align__(16) float Bs[BK][BN + 4];

    const int bz = blockIdx.z;
    A += (long long)bz * strideA;
    B += (long long)bz * strideB;
    C += (long long)bz * strideC;

    const int m0 = blockIdx.y * BM;
    const int n0 = blockIdx.x * BN;
    const int tid = threadIdx.x;
    const int tx = tid & 15;   // 0..15 -> column group
    const int ty = tid >> 4;   // 0..15 -> row group

    float acc[TM][TN];
    #pragma unroll
    for (int i = 0; i < TM; i++)
        #pragma unroll
        for (int j = 0; j < TN; j++)
            acc[i][j] = 0.0f;

    for (int k0 = 0; k0 < K; k0 += BK) {
        // ---- load A tile: 128 rows x 16 cols, transposed into As[k][m]
        #pragma unroll
        for (int i = 0; i < 2; i++) {
            int idx = tid + i * NTHREADS;       // 0..511
            int r  = idx >> 2;                  // row within tile
            int cg = (idx & 3) << 2;            // k group
            float4 v = *reinterpret_cast<const float4*>(
                &A[(long long)(m0 + r) * K + k0 + cg]);
            As[cg + 0][r] = v.x;
            As[cg + 1][r] = v.y;
            As[cg + 2][r] = v.z;
            As[cg + 3][r] = v.w;
        }
        // ---- load B tile
        if (TRANS_B) {
            // B[N][K]: tile rows are n, contiguous along k. Transpose into Bs[k][n].
            #pragma unroll
            for (int i = 0; i < 2; i++) {
                int idx = tid + i * NTHREADS;
                int r  = idx >> 2;              // n within tile
                int cg = (idx & 3) << 2;        // k group
                float4 v = *reinterpret_cast<const float4*>(
                    &B[(long long)(n0 + r) * K + k0 + cg]);
                Bs[cg + 0][r] = v.x;
                Bs[cg + 1][r] = v.y;
                Bs[cg + 2][r] = v.z;
                Bs[cg + 3][r] = v.w;
            }
        } else {
            // B[K][N]: 16 rows x 128 cols contiguous.
            #pragma unroll
            for (int i = 0; i < 2; i++) {
                int idx = tid + i * NTHREADS;
                int r = idx >> 5;               // k row 0..15
                int c = (idx & 31) << 2;        // n col
                float4 v = *reinterpret_cast<const float4*>(
                    &B[(long long)(k0 + r) * N + n0 + c]);
                *reinterpret_cast<float4*>(&Bs[r][c]) = v;
            }
        }
        __syncthreads();

        #pragma unroll
        for (int k = 0; k < BK; k++) {
            float a[TM], b[TN];
            *reinterpret_cast<float4*>(&a[0]) = *reinterpret_cast<const float4*>(&As[k][ty * TM]);
            *reinterpret_cast<float4*>(&a[4]) = *reinterpret_cast<const float4*>(&As[k][ty * TM + 4]);
            *reinterpret_cast<float4*>(&b[0]) = *reinterpret_cast<const float4*>(&Bs[k][tx * TN]);
            *reinterpret_cast<float4*>(&b[4]) = *reinterpret_cast<const float4*>(&Bs[k][tx * TN + 4]);
            #pragma unroll
            for (int i = 0; i < TM; i++)
                #pragma unroll
                for (int j = 0; j < TN; j++)
                    acc[i][j] = __fmaf_rn(a[i], b[j], acc[i][j]);
        }
        __syncthreads();
    }

    // ---- epilogue
    if (XPOS_MODE == 0) {
        #pragma unroll
        for (int i = 0; i < TM; i++) {
            long long row = m0 + ty * TM + i;
            float* cp = &C[row * N + n0 + tx * TN];
            float4 v0 = make_float4(acc[i][0], acc[i][1], acc[i][2], acc[i][3]);
            float4 v1 = make_float4(acc[i][4], acc[i][5], acc[i][6], acc[i][7]);
            *reinterpret_cast<float4*>(cp)     = v0;
            *reinterpret_cast<float4*>(cp + 4) = v1;
        }
    } else {
        const float LN1E4 = 9.210340371976184f;  // ln(10000)
        #pragma unroll
        for (int i = 0; i < TM; i++) {
            int row = m0 + ty * TM + i;
            int l = row & (LL - 1);              // position within sequence
            float lf = (float)l;
            float power = lf * (1.0f / 512.0f);  // l / SCALE_BASE
            float out[TN];
            #pragma unroll
            for (int p = 0; p < TN / 2; p++) {
                int col = n0 + tx * TN + 2 * p;
                int jj = col >> 1;               // pair index 0..N/2-1
                float sv = (2.0f * (float)jj + 0.4f * (float)N) / (1.4f * (float)N);
                float scale = expf(power * logf(sv));
                if (XPOS_MODE == 2) scale = 1.0f / scale;
                // inv_freq = 10000^{-jj/(N/2)}
                float inv_freq = expf(-(float)jj * (2.0f / (float)N) * LN1E4);
                float theta = __fmul_rn(lf, inv_freq);
                float s, c;
                sincos_red(theta, &s, &c);
                s *= scale;
                c *= scale;
                float xe = acc[i][2 * p];
                float xo = acc[i][2 * p + 1];
                out[2 * p]     = xe * c - xo * s;
                out[2 * p + 1] = xo * c + xe * s;
            }
            float* cp = &C[(long long)row * N + n0 + tx * TN];
            float4 v0 = make_float4(out[0], out[1], out[2], out[3]);
            float4 v1 = make_float4(out[4], out[5], out[6], out[7]);
            *reinterpret_cast<float4*>(cp)     = v0;
            *reinterpret_cast<float4*>(cp + 4) = v1;
        }
    }
}

// Row-wise softmax over L, then multiply by D[q,k] = gamma^|q-k|.
// grid: (L, B), 256 threads, each thread owns 8 strided elements.
__global__ void softmax_d_kernel(float* __restrict__ S)
{
    const int q = blockIdx.x;
    float* row = S + ((size_t)blockIdx.y * LL + q) * (size_t)LL;
    const int tid = threadIdx.x;
    const int lane = tid & 31;
    const int warp = tid >> 5;
    const float LN_GAMMA = -0.10536051565782628f;  // ln(0.9)

    __shared__ float red[8];

    float v[8];
    float m = -INFINITY;
    #pragma unroll
    for (int i = 0; i < 8; i++) {
        v[i] = row[i * 256 + tid];
        m = fmaxf(m, v[i]);
    }
    #pragma unroll
    for (int o = 16; o > 0; o >>= 1)
        m = fmaxf(m, __shfl_xor_sync(0xffffffffu, m, o));
    if (lane == 0) red[warp] = m;
    __syncthreads();
    float mb = red[0];
    #pragma unroll
    for (int w = 1; w < 8; w++) mb = fmaxf(mb, red[w]);
    __syncthreads();

    float sum = 0.0f;
    #pragma unroll
    for (int i = 0; i < 8; i++) {
        v[i] = expf(v[i] - mb);
        sum += v[i];
    }
    #pragma unroll
    for (int o = 16; o > 0; o >>= 1)
        sum += __shfl_xor_sync(0xffffffffu, sum, o);
    if (lane == 0) red[warp] = sum;
    __syncthreads();
    float tot = 0.0f;
    #pragma unroll
    for (int w = 0; w < 8; w++) tot += red[w];
    float inv = 1.0f / tot;

    #pragma unroll
    for (int i = 0; i < 8; i++) {
        int k = i * 256 + tid;
        float d = expf(fabsf((float)(q - k)) * LN_GAMMA);
        row[k] = v[i] * d * inv;
    }
}

extern "C" void kernel_launch(void* const* d_in, const int* in_sizes, int n_in,
                              void* d_out, int out_size)
{
    const float* X  = (const float*)d_in[0];
    const float* WQ = (const float*)d_in[1];
    const float* WK = (const float*)d_in[2];
    const float* WV = (const float*)d_in[3];
    float* out = (float*)d_out;

    float *Q, *Kp, *V, *S;
    cudaGetSymbolAddress((void**)&Q,  g_Q);
    cudaGetSymbolAddress((void**)&Kp, g_K);
    cudaGetSymbolAddress((void**)&V,  g_V);
    cudaGetSymbolAddress((void**)&S,  g_S);

    const int M = BB * LL;   // 16384
    dim3 blk(NTHREADS);

    // 1) QKV projections with fused XPOS
    dim3 g1(DH / BN, M / BM, 1);
    gemm_kernel<1, false><<<g1, blk>>>(X, WQ, Q,  M, DH, HH, 0, 0, 0);
    gemm_kernel<2, false><<<g1, blk>>>(X, WK, Kp, M, DH, HH, 0, 0, 0);
    gemm_kernel<0, false><<<g1, blk>>>(X, WV, V,  M, DH, HH, 0, 0, 0);

    // 2) scores = Q @ K^T per batch
    dim3 g2(LL / BN, LL / BM, BB);
    gemm_kernel<0, true><<<g2, blk>>>(Q, Kp, S, LL, LL, DH,
                                      (long long)LL * DH, (long long)LL * DH,
                                      (long long)LL * LL);

    // 3) softmax over k, then * D
    dim3 g3(LL, BB);
    softmax_d_kernel<<<g3, blk>>>(S);

    // 4) out = P @ V per batch
    dim3 g4(DH / BN, LL / BM, BB);
    gemm_kernel<0, false><<<g4, blk>>>(S, V, out, LL, DH, LL,
                                       (long long)LL * LL, (long long)LL * DH,
                                       (long long)LL * DH);
}

// round 3
// speedup vs baseline: 2.4852x; 2.4852x over previous
#include <cuda_runtime.h>
#include <cuda_bf16.h>
#include <math.h>
#include <stdint.h>

// Problem constants (fixed by setup_inputs)
#define BB  8
#define LL  2048
#define HH  1024
#define DH  1024

#define TGN 256          // threads per GEMM CTA (8 warps)
#define BKF 32           // fp32 k-elements per tile

// smem: per stage, A tile 128x(32hi+32lo) bf16 = 16KB, B tile 16KB
#define TILE_BYTES  16384
#define OFF_B       16384
#define STAGE_BYTES 32768
#define SMEM_TOTAL  (2 * STAGE_BYTES)

// ---- scratch (static device globals; allocation-free) ----
__device__ float g_Q [(size_t)BB * LL * DH];
__device__ float g_K [(size_t)BB * LL * DH];
__device__ float g_Vt[(size_t)BB * LL * DH];          // V transposed per batch: [Dh][L]
__device__ float g_S [(size_t)BB * LL * LL];
__device__ float g_WtQ[(size_t)HH * DH];
__device__ float g_WtK[(size_t)HH * DH];
__device__ float g_WtV[(size_t)HH * DH];

// ======================= helpers =======================
__device__ __forceinline__ uint32_t smem_u32(const void* p) {
    uint32_t a;
    asm("{ .reg .u64 t; cvta.to.shared.u64 t, %1; cvt.u32.u64 %0, t; }" : "=r"(a) : "l"(p));
    return a;
}
__device__ __forceinline__ uint32_t sw128(uint32_t off) {
    return off ^ ((off >> 3) & 0x70);
}
__device__ __forceinline__ void ldsm_x4(uint32_t* r, uint32_t addr) {
    asm volatile("ldmatrix.sync.aligned.m8n8.x4.shared.b16 {%0,%1,%2,%3}, [%4];"
                 : "=r"(r[0]), "=r"(r[1]), "=r"(r[2]), "=r"(r[3]) : "r"(addr));
}
__device__ __forceinline__ void mma_bf16(float* c, const uint32_t* a,
                                         uint32_t b0, uint32_t b1) {
    asm volatile(
        "mma.sync.aligned.m16n8k16.row.col.f32.bf16.bf16.f32 "
        "{%0,%1,%2,%3}, {%4,%5,%6,%7}, {%8,%9}, {%0,%1,%2,%3};"
        : "+f"(c[0]), "+f"(c[1]), "+f"(c[2]), "+f"(c[3])
        : "r"(a[0]), "r"(a[1]), "r"(a[2]), "r"(a[3]), "r"(b0), "r"(b1));
}

// Cody-Waite reduced sincos (survives --use_fast_math; theta in [0, ~2100))
__device__ __forceinline__ void sincos_red(float theta, float* s, float* c) {
    const float INV_2PI = 0.15915494309189535f;
    const float PI2_HI  = 6.28318548202514648f;
    const float PI2_LO  = -1.7484555e-7f;
    float k = nearbyintf(theta * INV_2PI);
    float r = __fmaf_rn(-k, PI2_HI, theta);
    r = __fmaf_rn(-k, PI2_LO, r);
    sincosf(r, s, c);
}

// fp32x4 -> bf16 hi at col c4, bf16 lo at col 32+c4 (row r of a 128B-row tile)
__device__ __forceinline__ void split_store(char* tile, int r, int c4, float4 v) {
    __nv_bfloat162 h01 = __floats2bfloat162_rn(v.x, v.y);
    __nv_bfloat162 h23 = __floats2bfloat162_rn(v.z, v.w);
    float lx = v.x - __bfloat162float(h01.x);
    float ly = v.y - __bfloat162float(h01.y);
    float lz = v.z - __bfloat162float(h23.x);
    float lw = v.w - __bfloat162float(h23.y);
    __nv_bfloat162 l01 = __floats2bfloat162_rn(lx, ly);
    __nv_bfloat162 l23 = __floats2bfloat162_rn(lz, lw);
    uint2 hv = make_uint2(*(uint32_t*)&h01, *(uint32_t*)&h23);
    uint2 lv = make_uint2(*(uint32_t*)&l01, *(uint32_t*)&l23);
    uint32_t off_h = (uint32_t)(r * 128 + c4 * 2);
    *(uint2*)(tile + sw128(off_h))      = hv;
    *(uint2*)(tile + sw128(off_h + 64)) = lv;
}

// ======================= mma.sync GEMM =======================
// C[M,N] = A[M,K] * B[N,K]^T   (both K-major fp32; bf16 hi/lo 3-product split)
// MODE: 0 = plain, 1 = XPOS (Q), 2 = XPOS inverse (K), 3 = store transposed (V^T)
template<int MODE>
__global__ void __launch_bounds__(TGN, 1)
tgemm(const float* __restrict__ A, const float* __restrict__ B, float* __restrict__ C,
      int M, int N, int K, long long sA, long long sB, long long sC)
{
    extern __shared__ char smem[];
    const int tid  = threadIdx.x;
    const int wid  = tid >> 5;
    const int lane = tid & 31;

    A += (long long)blockIdx.z * sA;
    B += (long long)blockIdx.z * sB;
    C += (long long)blockIdx.z * sC;
    const int m0 = blockIdx.y * 128;
    const int n0 = blockIdx.x * 128;

    // warp layout: 2 (m) x 4 (n); warp tile 64(m) x 32(n)
    const int wm = (wid & 1) * 64;
    const int wn = (wid >> 1) * 32;

    float acc[16][4];
    #pragma unroll
    for (int i = 0; i < 16; i++)
        #pragma unroll
        for (int j = 0; j < 4; j++) acc[i][j] = 0.0f;

    // per-lane ldmatrix source rows (within 128-row tile)
    const int rowA = wm + (lane & 15);          // + mt*16
    const int chA  = lane >> 4;                 // k chunk (8 bf16)
    const int rowB = wn + (lane & 7) + ((lane & 16) >> 1);  // + pair*16
    const int chB  = (lane >> 3) & 1;

    const int nk = K / BKF;
    float4 fa[4], fb[4];

    // ---- prologue: k-tile 0 -> stage 0
    #pragma unroll
    for (int p = 0; p < 4; p++) {
        int idx = tid + p * TGN;                // 0..1023
        int r = idx >> 3, c4 = (idx & 7) << 2;
        fa[p] = *(const float4*)(A + (size_t)(m0 + r) * K + c4);
        fb[p] = *(const float4*)(B + (size_t)(n0 + r) * K + c4);
    }
    #pragma unroll
    for (int p = 0; p < 4; p++) {
        int idx = tid + p * TGN;
        int r = idx >> 3, c4 = (idx & 7) << 2;
        split_store(smem,         r, c4, fa[p]);
        split_store(smem + OFF_B, r, c4, fb[p]);
    }
    __syncthreads();

    for (int it = 0; it < nk; ++it) {
        const bool more = (it + 1) < nk;
        // issue next-tile global loads first (hidden under mma)
        if (more) {
            const int k0 = (it + 1) * BKF;
            #pragma unroll
            for (int p = 0; p < 4; p++) {
                int idx = tid + p * TGN;
                int r = idx >> 3, c4 = (idx & 7) << 2;
                fa[p] = *(const float4*)(A + (size_t)(m0 + r) * K + k0 + c4);
                fb[p] = *(const float4*)(B + (size_t)(n0 + r) * K + k0 + c4);
            }
        }

        // ---- compute on current stage
        {
            const uint32_t abase = smem_u32(smem) + (uint32_t)((it & 1) * STAGE_BYTES);
            const uint32_t bbase = abase + OFF_B;
            #pragma unroll
            for (int ks = 0; ks < 2; ks++) {
                uint32_t Ah[16], Al[16], Bh[8], Bl[8];
                const int colh = ks * 16;       // bf16 col of hi
                #pragma unroll
                for (int mt = 0; mt < 4; mt++) {
                    uint32_t offh = (uint32_t)((rowA + mt * 16) * 128 + (colh + chA * 8) * 2);
                    ldsm_x4(Ah + mt * 4, abase + sw128(offh));
                    ldsm_x4(Al + mt * 4, abase + sw128(offh + 64));
                }
                #pragma unroll
                for (int pr = 0; pr < 2; pr++) {
                    uint32_t offh = (uint32_t)((rowB + pr * 16) * 128 + (colh + chB * 8) * 2);
                    ldsm_x4(Bh + pr * 4, bbase + sw128(offh));
                    ldsm_x4(Bl + pr * 4, bbase + sw128(offh + 64));
                }
                #pragma unroll
                for (int mt = 0; mt < 4; mt++)
                    #pragma unroll
                    for (int nt = 0; nt < 4; nt++) {
                        float* c = acc[mt * 4 + nt];
                        const int bi = (nt >> 1) * 4 + (nt & 1) * 2;
                        mma_bf16(c, Ah + mt * 4, Bh[bi], Bh[bi + 1]);
                        mma_bf16(c, Ah + mt * 4, Bl[bi], Bl[bi + 1]);
                        mma_bf16(c, Al + mt * 4, Bh[bi], Bh[bi + 1]);
                    }
            }
        }

        // ---- store next tile into other stage
        if (more) {
            char* stage = smem + ((it + 1) & 1) * STAGE_BYTES;
            #pragma unroll
            for (int p = 0; p < 4; p++) {
                int idx = tid + p * TGN;
                int r = idx >> 3, c4 = (idx & 7) << 2;
                split_store(stage,         r, c4, fa[p]);
                split_store(stage + OFF_B, r, c4, fb[p]);
            }
        }
        __syncthreads();
    }

    // ======================= epilogue =======================
    if (MODE == 0) {
        #pragma unroll
        for (int mt = 0; mt < 4; mt++) {
            const int r = m0 + wm + mt * 16 + (lane >> 2);
            #pragma unroll
            for (int nt = 0; nt < 4; nt++) {
                const int cc = n0 + wn + nt * 8 + (lane & 3) * 2;
                float* c = acc[mt * 4 + nt];
                *(float2*)(C + (size_t)r * N + cc)       = make_float2(c[0], c[1]);
                *(float2*)(C + (size_t)(r + 8) * N + cc) = make_float2(c[2], c[3]);
            }
        }
    } else if (MODE == 3) {
        // C is V^T: [Dh][L] per batch; m -> (b, l), col cc -> Dh row
        #pragma unroll
        for (int mt = 0; mt < 4; mt++) {
            const int m = m0 + wm + mt * 16 + (lane >> 2);
            const int b = m >> 11;
            const int l = m & (LL - 1);
            float* base = C + (size_t)b * DH * LL;
            #pragma unroll
            for (int nt = 0; nt < 4; nt++) {
                const int cc = n0 + wn + nt * 8 + (lane & 3) * 2;
                float* c = acc[mt * 4 + nt];
                base[(size_t)cc * LL + l]           = c[0];
                base[(size_t)(cc + 1) * LL + l]     = c[1];
                base[(size_t)cc * LL + l + 8]       = c[2];
                base[(size_t)(cc + 1) * LL + l + 8] = c[3];
            }
        }
    } else {
        const float LN1E4 = 9.210340371976184f;
        #pragma unroll
        for (int nt = 0; nt < 4; nt++) {
            const int cc = n0 + wn + nt * 8 + (lane & 3) * 2;
            const int jj = cc >> 1;
            float lgsv = logf((2.0f * (float)jj + 0.4f * (float)N) / (1.4f * (float)N));
            if (MODE == 2) lgsv = -lgsv;
            const float invf = expf(-(float)jj * (2.0f / (float)N) * LN1E4);
            #pragma unroll
            for (int mt = 0; mt < 4; mt++) {
                const int r = m0 + wm + mt * 16 + (lane >> 2);
                float* c = acc[mt * 4 + nt];
                #pragma unroll
                for (int h = 0; h < 2; h++) {
                    const int row = r + h * 8;
                    const int l = row & (LL - 1);
                    const float lf = (float)l;
                    float scale = expf(lf * (1.0f / 512.0f) * lgsv);
                    float s, co;
                    sincos_red(lf * invf, &s, &co);
                    s *= scale; co *= scale;
                    float xe = c[2 * h], xo = c[2 * h + 1];
                    *(float2*)(C + (size_t)row * N + cc) =
                        make_float2(xe * co - xo * s, xo * co + xe * s);
                }
            }
        }
    }
}

// ======================= transpose (weights) =======================
__global__ void transpose1024(const float* __restrict__ in, float* __restrict__ out) {
    __shared__ float t[32][33];
    const int bx = blockIdx.x * 32, by = blockIdx.y * 32;
    #pragma unroll
    for (int i = threadIdx.y; i < 32; i += 8)
        t[i][threadIdx.x] = in[(size_t)(by + i) * HH + bx + threadIdx.x];
    __syncthreads();
    #pragma unroll
    for (int i = threadIdx.y; i < 32; i += 8)
        out[(size_t)(bx + i) * HH + by + threadIdx.x] = t[threadIdx.x][i];
}

// ======================= softmax * D =======================
__global__ void softmax_d_kernel(float* __restrict__ S) {
    const int q = blockIdx.x;
    float* row = S + ((size_t)blockIdx.y * LL + q) * (size_t)LL;
    const int tid = threadIdx.x;
    const int lane = tid & 31;
    const int warp = tid >> 5;
    const float LN_GAMMA = -0.10536051565782628f;  // ln(0.9)

    __shared__ float red[8];

    float v[8];
    float m = -INFINITY;
    #pragma unroll
    for (int i = 0; i < 8; i++) {
        v[i] = row[i * 256 + tid];
        m = fmaxf(m, v[i]);
    }
    #pragma unroll
    for (int o = 16; o > 0; o >>= 1)
        m = fmaxf(m, __shfl_xor_sync(0xffffffffu, m, o));
    if (lane == 0) red[warp] = m;
    __syncthreads();
    float mb = red[0];
    #pragma unroll
    for (int w = 1; w < 8; w++) mb = fmaxf(mb, red[w]);
    __syncthreads();

    float sum = 0.0f;
    #pragma unroll
    for (int i = 0; i < 8; i++) {
        v[i] = expf(v[i] - mb);
        sum += v[i];
    }
    #pragma unroll
    for (int o = 16; o > 0; o >>= 1)
        sum += __shfl_xor_sync(0xffffffffu, sum, o);
    if (lane == 0) red[warp] = sum;
    __syncthreads();
    float tot = 0.0f;
    #pragma unroll
    for (int w = 0; w < 8; w++) tot += red[w];
    float inv = 1.0f / tot;

    #pragma unroll
    for (int i = 0; i < 8; i++) {
        int k = i * 256 + tid;
        float d = expf(fabsf((float)(q - k)) * LN_GAMMA);
        row[k] = v[i] * d * inv;
    }
}

// ======================= launcher =======================
extern "C" void kernel_launch(void* const* d_in, const int* in_sizes, int n_in,
                              void* d_out, int out_size)
{
    const float* X  = (const float*)d_in[0];
    const float* WQ = (const float*)d_in[1];
    const float* WK = (const float*)d_in[2];
    const float* WV = (const float*)d_in[3];
    float* out = (float*)d_out;

    float *Q, *Kp, *Vt, *S, *WtQ, *WtK, *WtV;
    cudaGetSymbolAddress((void**)&Q,   g_Q);
    cudaGetSymbolAddress((void**)&Kp,  g_K);
    cudaGetSymbolAddress((void**)&Vt,  g_Vt);
    cudaGetSymbolAddress((void**)&S,   g_S);
    cudaGetSymbolAddress((void**)&WtQ, g_WtQ);
    cudaGetSymbolAddress((void**)&WtK, g_WtK);
    cudaGetSymbolAddress((void**)&WtV, g_WtV);

    cudaFuncSetAttribute(tgemm<0>, cudaFuncAttributeMaxDynamicSharedMemorySize, SMEM_TOTAL);
    cudaFuncSetAttribute(tgemm<1>, cudaFuncAttributeMaxDynamicSharedMemorySize, SMEM_TOTAL);
    cudaFuncSetAttribute(tgemm<2>, cudaFuncAttributeMaxDynamicSharedMemorySize, SMEM_TOTAL);
    cudaFuncSetAttribute(tgemm<3>, cudaFuncAttributeMaxDynamicSharedMemorySize, SMEM_TOTAL);

    const int M = BB * LL;  // 16384

    // 0) pre-transpose weights to [N][K]
    dim3 tb(32, 8), tg(32, 32);
    transpose1024<<<tg, tb>>>(WQ, WtQ);
    transpose1024<<<tg, tb>>>(WK, WtK);
    transpose1024<<<tg, tb>>>(WV, WtV);

    // 1) projections (XPOS fused for Q/K; V written transposed)
    dim3 g1(DH / 128, M / 128, 1);
    tgemm<1><<<g1, TGN, SMEM_TOTAL>>>(X, WtQ, Q,  M, DH, HH, 0, 0, 0);
    tgemm<2><<<g1, TGN, SMEM_TOTAL>>>(X, WtK, Kp, M, DH, HH, 0, 0, 0);
    tgemm<3><<<g1, TGN, SMEM_TOTAL>>>(X, WtV, Vt, M, DH, HH, 0, 0, 0);

    // 2) scores = Q K^T per batch
    dim3 g2(LL / 128, LL / 128, BB);
    tgemm<0><<<g2, TGN, SMEM_TOTAL>>>(Q, Kp, S, LL, LL, DH,
                                      (long long)LL * DH, (long long)LL * DH,
                                      (long long)LL * LL);

    // 3) softmax * D
    softmax_d_kernel<<<dim3(LL, BB), 256>>>(S);

    // 4) out = P V per batch (B operand = V^T, [Dh][L] K-major)
    dim3 g4(DH / 128, LL / 128, BB);
    tgemm<0><<<g4, TGN, SMEM_TOTAL>>>(S, Vt, out, LL, DH, LL,
                                      (long long)LL * LL, (long long)LL * DH,
                                      (long long)LL * DH);
}

// round 4
// speedup vs baseline: 4.0644x; 1.6355x over previous
#include <cuda_runtime.h>
#include <cuda_fp16.h>
#include <math.h>
#include <stdint.h>

// Problem constants (fixed by setup_inputs)
#define BB  8
#define LL  2048
#define HH  1024
#define DH  1024

#define TGN 256          // 8 warps per CTA
#define STAGES 4
#define OFF_AL  16384
#define OFF_B   32768
#define STAGE_BYTES 49152
#define SMEM_TOTAL (STAGES * STAGE_BYTES)   // 192 KB

// ---- scratch (static device globals; allocation-free) ----
__device__ __half g_Xh [(size_t)BB * LL * HH];
__device__ __half g_Xl [(size_t)BB * LL * HH];
__device__ __half g_WhQ[(size_t)HH * DH];
__device__ __half g_WhK[(size_t)HH * DH];
__device__ __half g_WhV[(size_t)HH * DH];
__device__ __half g_Qh [(size_t)BB * LL * DH];
__device__ __half g_Ql [(size_t)BB * LL * DH];
__device__ __half g_Kh [(size_t)BB * LL * DH];
__device__ __half g_Vth[(size_t)BB * LL * DH];       // V^T per batch: [Dh][L]
__device__ float  g_S  [(size_t)BB * LL * LL];
__device__ __half g_Ph [(size_t)BB * LL * LL];
__device__ __half g_Pl [(size_t)BB * LL * LL];

// ======================= helpers =======================
__device__ __forceinline__ uint32_t smem_u32(const void* p) {
    uint32_t a;
    asm("{ .reg .u64 t; cvta.to.shared.u64 t, %1; cvt.u32.u64 %0, t; }" : "=r"(a) : "l"(p));
    return a;
}
__device__ __forceinline__ uint32_t sw128(uint32_t off) {
    return off ^ ((off >> 3) & 0x70);
}
__device__ __forceinline__ void cpa16(uint32_t dst, const void* src) {
    asm volatile("cp.async.cg.shared.global [%0], [%1], 16;" :: "r"(dst), "l"(src));
}
__device__ __forceinline__ void cp_commit() {
    asm volatile("cp.async.commit_group;" ::: "memory");
}
template<int N> __device__ __forceinline__ void cp_wait() {
    asm volatile("cp.async.wait_group %0;" :: "n"(N) : "memory");
}
__device__ __forceinline__ void ldsm_x4(uint32_t* r, uint32_t addr) {
    asm volatile("ldmatrix.sync.aligned.m8n8.x4.shared.b16 {%0,%1,%2,%3}, [%4];"
                 : "=r"(r[0]), "=r"(r[1]), "=r"(r[2]), "=r"(r[3]) : "r"(addr));
}
__device__ __forceinline__ void mma_f16(float* c, const uint32_t* a,
                                        uint32_t b0, uint32_t b1) {
    asm volatile(
        "mma.sync.aligned.m16n8k16.row.col.f32.f16.f16.f32 "
        "{%0,%1,%2,%3}, {%4,%5,%6,%7}, {%8,%9}, {%0,%1,%2,%3};"
        : "+f"(c[0]), "+f"(c[1]), "+f"(c[2]), "+f"(c[3])
        : "r"(a[0]), "r"(a[1]), "r"(a[2]), "r"(a[3]), "r"(b0), "r"(b1));
}

// Cody-Waite reduced sincos (survives --use_fast_math; theta in [0, ~2100))
__device__ __forceinline__ void sincos_red(float theta, float* s, float* c) {
    const float INV_2PI = 0.15915494309189535f;
    const float PI2_HI  = 6.28318548202514648f;
    const float PI2_LO  = -1.7484555e-7f;
    float k = nearbyintf(theta * INV_2PI);
    float r = __fmaf_rn(-k, PI2_HI, theta);
    r = __fmaf_rn(-k, PI2_LO, r);
    sincosf(r, s, c);
}

__device__ __forceinline__ void split_h(float x, __half& h, __half& l) {
    h = __float2half_rn(x);
    l = __float2half_rn(x - __half2float(h));
}

// ======================= mma.sync fp16 GEMM =======================
// C[M,N] = A[M,K] * B[N,K]^T ; A = Ah + Al (fp16 hi/lo pair), B = fp16.
// 2 products: Ah*B + Al*B.
// MODE: 0 = fp32 C, 1 = XPOS -> Ch+Cl, 2 = XPOS inverse -> Ch, 3 = transposed -> Ch
template<int MODE>
__global__ void __launch_bounds__(TGN, 1)
tgemm(const __half* __restrict__ Ah, const __half* __restrict__ Al,
      const __half* __restrict__ Bh,
      float* __restrict__ C, __half* __restrict__ Ch, __half* __restrict__ Cl,
      int M, int N, int K,
      long long sA, long long sB, long long sC)
{
    extern __shared__ char smem[];
    const uint32_t sb = smem_u32(smem);
    const int tid  = threadIdx.x;
    const int wid  = tid >> 5;
    const int lane = tid & 31;

    Ah += (long long)blockIdx.z * sA;
    Al += (long long)blockIdx.z * sA;
    Bh += (long long)blockIdx.z * sB;
    const int m0 = blockIdx.y * 128;
    const int n0 = blockIdx.x * 128;

    // warp layout: 2 (m) x 4 (n); warp tile 64(m) x 32(n)
    const int wm = (wid & 1) * 64;
    const int wn = (wid >> 1) * 32;

    float acc[16][4];
    #pragma unroll
    for (int i = 0; i < 16; i++)
        #pragma unroll
        for (int j = 0; j < 4; j++) acc[i][j] = 0.0f;

    const int rowA = wm + (lane & 15);
    const int chA  = lane >> 4;
    const int rowB = wn + (lane & 7) + ((lane & 16) >> 1);
    const int chB  = (lane >> 3) & 1;

    const int nk = K >> 6;          // k-tile = 64 halves (128B rows)

    // per-thread cp.async assignments: 1024 16B-chunks per 16KB tile
    const int cr = tid >> 3;              // row base helper (with p offset)
    const int cch = tid & 7;              // chunk in row

    auto issue = [&](int kt, int stg) {
        const uint32_t sbase = sb + (uint32_t)stg * STAGE_BYTES;
        #pragma unroll
        for (int p = 0; p < 4; p++) {
            int r = cr + p * 32;          // (tid + p*256) >> 3
            uint32_t d = sw128((uint32_t)(r * 128 + cch * 16));
            const __half* ga = Ah + (size_t)(m0 + r) * K + kt * 64 + cch * 8;
            const __half* gl = Al + (size_t)(m0 + r) * K + kt * 64 + cch * 8;
            const __half* gb = Bh + (size_t)(n0 + r) * K + kt * 64 + cch * 8;
            cpa16(sbase + d, ga);
            cpa16(sbase + OFF_AL + d, gl);
            cpa16(sbase + OFF_B + d, gb);
        }
        cp_commit();
    };

    // prologue: stages 0..2
    issue(0, 0); issue(1, 1); issue(2, 2);

    for (int it = 0; it < nk; ++it) {
        cp_wait<2>();
        __syncthreads();

        // refill slot (it+3)&3 (== slot it-1, finished last iteration)
        if (it + 3 < nk) issue(it + 3, (it + 3) & 3);
        else cp_commit();

        // compute on stage it&3
        const uint32_t abase = sb + (uint32_t)((it & 3) * STAGE_BYTES);
        #pragma unroll
        for (int ks = 0; ks < 4; ks++) {
            uint32_t Afh[16], Afl[16], Bf[8];
            #pragma unroll
            for (int mt = 0; mt < 4; mt++) {
                uint32_t off = sw128((uint32_t)((rowA + mt * 16) * 128 + ks * 32 + chA * 16));
                ldsm_x4(Afh + mt * 4, abase + off);
                ldsm_x4(Afl + mt * 4, abase + OFF_AL + off);
            }
            #pragma unroll
            for (int pr = 0; pr < 2; pr++) {
                uint32_t off = sw128((uint32_t)((rowB + pr * 16) * 128 + ks * 32 + chB * 16));
                ldsm_x4(Bf + pr * 4, abase + OFF_B + off);
            }
            #pragma unroll
            for (int mt = 0; mt < 4; mt++)
                #pragma unroll
                for (int nt = 0; nt < 4; nt++) {
                    float* c = acc[mt * 4 + nt];
                    const int bi = (nt >> 1) * 4 + (nt & 1) * 2;
                    mma_f16(c, Afh + mt * 4, Bf[bi], Bf[bi + 1]);
                    mma_f16(c, Afl + mt * 4, Bf[bi], Bf[bi + 1]);
                }
        }
    }

    // ======================= epilogue =======================
    if (MODE == 0) {
        float* Cb = C + (long long)blockIdx.z * sC;
        #pragma unroll
        for (int mt = 0; mt < 4; mt++) {
            const int r = m0 + wm + mt * 16 + (lane >> 2);
            #pragma unroll
            for (int nt = 0; nt < 4; nt++) {
                const int cc = n0 + wn + nt * 8 + (lane & 3) * 2;
                float* c = acc[mt * 4 + nt];
                *(float2*)(Cb + (size_t)r * N + cc)       = make_float2(c[0], c[1]);
                *(float2*)(Cb + (size_t)(r + 8) * N + cc) = make_float2(c[2], c[3]);
            }
        }
    } else if (MODE == 3) {
        // transposed fp16 store: Ch is [Dh][L] per batch
        #pragma unroll
        for (int mt = 0; mt < 4; mt++) {
            const int m = m0 + wm + mt * 16 + (lane >> 2);
            const int b = m >> 11;
            const int l = m & (LL - 1);
            __half* base = Ch + (size_t)b * DH * LL;
            #pragma unroll
            for (int nt = 0; nt < 4; nt++) {
                const int cc = n0 + wn + nt * 8 + (lane & 3) * 2;
                float* c = acc[mt * 4 + nt];
                base[(size_t)cc * LL + l]           = __float2half_rn(c[0]);
                base[(size_t)(cc + 1) * LL + l]     = __float2half_rn(c[1]);
                base[(size_t)cc * LL + l + 8]       = __float2half_rn(c[2]);
                base[(size_t)(cc + 1) * LL + l + 8] = __float2half_rn(c[3]);
            }
        }
    } else {
        const float LN1E4 = 9.210340371976184f;
        #pragma unroll
        for (int nt = 0; nt < 4; nt++) {
            const int cc = n0 + wn + nt * 8 + (lane & 3) * 2;
            const int jj = cc >> 1;
            float lgsv = logf((2.0f * (float)jj + 0.4f * (float)N) / (1.4f * (float)N));
            if (MODE == 2) lgsv = -lgsv;
            const float invf = expf(-(float)jj * (2.0f / (float)N) * LN1E4);
            #pragma unroll
            for (int mt = 0; mt < 4; mt++) {
                const int r = m0 + wm + mt * 16 + (lane >> 2);
                float* c = acc[mt * 4 + nt];
                #pragma unroll
                for (int h = 0; h < 2; h++) {
                    const int row = r + h * 8;
                    const int l = row & (LL - 1);
                    const float lf = (float)l;
                    float scale = expf(lf * (1.0f / 512.0f) * lgsv);
                    float s, co;
                    sincos_red(lf * invf, &s, &co);
                    s *= scale; co *= scale;
                    float xe = c[2 * h], xo = c[2 * h + 1];
                    float o0 = xe * co - xo * s;
                    float o1 = xo * co + xe * s;
                    if (MODE == 1) {
                        __half h0, l0, h1, l1;
                        split_h(o0, h0, l0);
                        split_h(o1, h1, l1);
                        *(__half2*)(Ch + (size_t)row * N + cc) = __halves2half2(h0, h1);
                        *(__half2*)(Cl + (size_t)row * N + cc) = __halves2half2(l0, l1);
                    } else {
                        *(__half2*)(Ch + (size_t)row * N + cc) =
                            __halves2half2(__float2half_rn(o0), __float2half_rn(o1));
                    }
                }
            }
        }
    }
}

// ======================= X split (fp32 -> fp16 hi/lo) =======================
__global__ void split_x(const float* __restrict__ in,
                        __half* __restrict__ oh, __half* __restrict__ ol, int n4)
{
    int i = blockIdx.x * blockDim.x + threadIdx.x;
    if (i >= n4) return;
    float4 v = ((const float4*)in)[i];
    __half h0, l0, h1, l1, h2, l2, h3, l3;
    split_h(v.x, h0, l0); split_h(v.y, h1, l1);
    split_h(v.z, h2, l2); split_h(v.w, h3, l3);
    ((__half2*)oh)[2 * i]     = __halves2half2(h0, h1);
    ((__half2*)oh)[2 * i + 1] = __halves2half2(h2, h3);
    ((__half2*)ol)[2 * i]     = __halves2half2(l0, l1);
    ((__half2*)ol)[2 * i + 1] = __halves2half2(l2, l3);
}

// ======================= weight transpose + fp16 round =======================
__global__ void transpose_h(const float* __restrict__ in, __half* __restrict__ out) {
    __shared__ float t[32][33];
    const int bx = blockIdx.x * 32, by = blockIdx.y * 32;
    #pragma unroll
    for (int i = threadIdx.y; i < 32; i += 8)
        t[i][threadIdx.x] = in[(size_t)(by + i) * DH + bx + threadIdx.x];
    __syncthreads();
    #pragma unroll
    for (int i = threadIdx.y; i < 32; i += 8)
        out[(size_t)(bx + i) * HH + by + threadIdx.x] =
            __float2half_rn(t[threadIdx.x][i]);
}

// ======================= softmax * D -> fp16 hi/lo =======================
__global__ void softmax_d_kernel(const float* __restrict__ S,
                                 __half* __restrict__ Ph, __half* __restrict__ Pl)
{
    const int q = blockIdx.x;
    const size_t ro = ((size_t)blockIdx.y * LL + q) * (size_t)LL;
    const float* row = S + ro;
    const int tid = threadIdx.x;
    const int lane = tid & 31;
    const int warp = tid >> 5;
    const float LN_GAMMA = -0.10536051565782628f;  // ln(0.9)

    __shared__ float red[8];

    float v[8];
    float m = -INFINITY;
    #pragma unroll
    for (int i = 0; i < 8; i++) {
        v[i] = row[i * 256 + tid];
        m = fmaxf(m, v[i]);
    }
    #pragma unroll
    for (int o = 16; o > 0; o >>= 1)
        m = fmaxf(m, __shfl_xor_sync(0xffffffffu, m, o));
    if (lane == 0) red[warp] = m;
    __syncthreads();
    float mb = red[0];
    #pragma unroll
    for (int w = 1; w < 8; w++) mb = fmaxf(mb, red[w]);
    __syncthreads();

    float sum = 0.0f;
    #pragma unroll
    for (int i = 0; i < 8; i++) {
        v[i] = expf(v[i] - mb);
        sum += v[i];
    }
    #pragma unroll
    for (int o = 16; o > 0; o >>= 1)
        sum += __shfl_xor_sync(0xffffffffu, sum, o);
    if (lane == 0) red[warp] = sum;
    __syncthreads();
    float tot = 0.0f;
    #pragma unroll
    for (int w = 0; w < 8; w++) tot += red[w];
    float inv = 1.0f / tot;

    #pragma unroll
    for (int i = 0; i < 8; i++) {
        int k = i * 256 + tid;
        float d = expf(fabsf((float)(q - k)) * LN_GAMMA);
        float p = v[i] * d * inv;
        __half h, l;
        split_h(p, h, l);
        Ph[ro + k] = h;
        Pl[ro + k] = l;
    }
}

// ======================= launcher =======================
extern "C" void kernel_launch(void* const* d_in, const int* in_sizes, int n_in,
                              void* d_out, int out_size)
{
    const float* X  = (const float*)d_in[0];
    const float* WQ = (const float*)d_in[1];
    const float* WK = (const float*)d_in[2];
    const float* WV = (const float*)d_in[3];
    float* out = (float*)d_out;

    __half *Xh, *Xl, *WhQ, *WhK, *WhV, *Qh, *Ql, *Kh, *Vth, *Ph, *Pl;
    float* S;
    cudaGetSymbolAddress((void**)&Xh,  g_Xh);
    cudaGetSymbolAddress((void**)&Xl,  g_Xl);
    cudaGetSymbolAddress((void**)&WhQ, g_WhQ);
    cudaGetSymbolAddress((void**)&WhK, g_WhK);
    cudaGetSymbolAddress((void**)&WhV, g_WhV);
    cudaGetSymbolAddress((void**)&Qh,  g_Qh);
    cudaGetSymbolAddress((void**)&Ql,  g_Ql);
    cudaGetSymbolAddress((void**)&Kh,  g_Kh);
    cudaGetSymbolAddress((void**)&Vth, g_Vth);
    cudaGetSymbolAddress((void**)&S,   g_S);
    cudaGetSymbolAddress((void**)&Ph,  g_Ph);
    cudaGetSymbolAddress((void**)&Pl,  g_Pl);

    cudaFuncSetAttribute(tgemm<0>, cudaFuncAttributeMaxDynamicSharedMemorySize, SMEM_TOTAL);
    cudaFuncSetAttribute(tgemm<1>, cudaFuncAttributeMaxDynamicSharedMemorySize, SMEM_TOTAL);
    cudaFuncSetAttribute(tgemm<2>, cudaFuncAttributeMaxDynamicSharedMemorySize, SMEM_TOTAL);
    cudaFuncSetAttribute(tgemm<3>, cudaFuncAttributeMaxDynamicSharedMemorySize, SMEM_TOTAL);

    const int M = BB * LL;  // 16384

    // 0) operand preparation
    int n4 = M * HH / 4;
    split_x<<<(n4 + 255) / 256, 256>>>(X, Xh, Xl, n4);
    dim3 tb(32, 8), tg(32, 32);
    transpose_h<<<tg, tb>>>(WQ, WhQ);
    transpose_h<<<tg, tb>>>(WK, WhK);
    transpose_h<<<tg, tb>>>(WV, WhV);

    // 1) projections
    dim3 g1(DH / 128, M / 128, 1);
    tgemm<1><<<g1, TGN, SMEM_TOTAL>>>(Xh, Xl, WhQ, nullptr, Qh, Ql, M, DH, HH, 0, 0, 0);
    tgemm<2><<<g1, TGN, SMEM_TOTAL>>>(Xh, Xl, WhK, nullptr, Kh, nullptr, M, DH, HH, 0, 0, 0);
    tgemm<3><<<g1, TGN, SMEM_TOTAL>>>(Xh, Xl, WhV, nullptr, Vth, nullptr, M, DH, HH, 0, 0, 0);

    // 2) scores = Q K^T per batch -> fp32 S
    dim3 g2(LL / 128, LL / 128, BB);
    tgemm<0><<<g2, TGN, SMEM_TOTAL>>>(Qh, Ql, Kh, S, nullptr, nullptr, LL, LL, DH,
                                      (long long)LL * DH, (long long)LL * DH,
                                      (long long)LL * LL);

    // 3) softmax * D -> fp16 hi/lo P
    softmax_d_kernel<<<dim3(LL, BB), 256>>>(S, Ph, Pl);

    // 4) out = P V per batch (B = V^T fp16, [Dh][L] K-major)
    dim3 g4(DH / 128, LL / 128, BB);
    tgemm<0><<<g4, TGN, SMEM_TOTAL>>>(Ph, Pl, Vth, out, nullptr, nullptr, LL, DH, LL,
                                      (long long)LL * LL, (long long)DH * LL,
                                      (long long)LL * DH);
}

// round 5
// speedup vs baseline: 6.2737x; 1.5436x over previous
#include <cuda_runtime.h>
#include <cuda_fp16.h>
#include <math.h>
#include <stdint.h>

// Problem constants (fixed by setup_inputs)
#define BB  8
#define LL  2048
#define HH  1024
#define DH  1024

#define TGN 256          // 8 warps per CTA
#define STAGES 5
#define OFF_B   16384
#define STAGE_BYTES 32768
#define SMEM_TOTAL (STAGES * STAGE_BYTES)   // 160 KB

// ---- scratch (static device globals; allocation-free) ----
__device__ __half g_Xh [(size_t)BB * LL * HH];
__device__ __half g_Wt [(size_t)3 * HH * DH];        // rows 0-1023: WQ^T, 1024-2047: WK^T, 2048-3071: WV^T
__device__ __half g_Qh [(size_t)BB * LL * DH];
__device__ __half g_Kh [(size_t)BB * LL * DH];
__device__ __half g_Vth[(size_t)BB * LL * DH];       // V^T per batch: [Dh][L]
__device__ float  g_S  [(size_t)BB * LL * LL];
__device__ __half g_Ph [(size_t)BB * LL * LL];

// ======================= helpers =======================
__device__ __forceinline__ uint32_t smem_u32(const void* p) {
    uint32_t a;
    asm("{ .reg .u64 t; cvta.to.shared.u64 t, %1; cvt.u32.u64 %0, t; }" : "=r"(a) : "l"(p));
    return a;
}
__device__ __forceinline__ uint32_t sw128(uint32_t off) {
    return off ^ ((off >> 3) & 0x70);
}
__device__ __forceinline__ void cpa16(uint32_t dst, const void* src) {
    asm volatile("cp.async.cg.shared.global [%0], [%1], 16;" :: "r"(dst), "l"(src));
}
__device__ __forceinline__ void cp_commit() {
    asm volatile("cp.async.commit_group;" ::: "memory");
}
template<int N> __device__ __forceinline__ void cp_wait() {
    asm volatile("cp.async.wait_group %0;" :: "n"(N) : "memory");
}
__device__ __forceinline__ void ldsm_x4(uint32_t* r, uint32_t addr) {
    asm volatile("ldmatrix.sync.aligned.m8n8.x4.shared.b16 {%0,%1,%2,%3}, [%4];"
                 : "=r"(r[0]), "=r"(r[1]), "=r"(r[2]), "=r"(r[3]) : "r"(addr));
}
__device__ __forceinline__ void mma_f16(float* c, const uint32_t* a,
                                        uint32_t b0, uint32_t b1) {
    asm volatile(
        "mma.sync.aligned.m16n8k16.row.col.f32.f16.f16.f32 "
        "{%0,%1,%2,%3}, {%4,%5,%6,%7}, {%8,%9}, {%0,%1,%2,%3};"
        : "+f"(c[0]), "+f"(c[1]), "+f"(c[2]), "+f"(c[3])
        : "r"(a[0]), "r"(a[1]), "r"(a[2]), "r"(a[3]), "r"(b0), "r"(b1));
}

// Cody-Waite reduced sincos (survives --use_fast_math; theta in [0, ~2100))
__device__ __forceinline__ void sincos_red(float theta, float* s, float* c) {
    const float INV_2PI = 0.15915494309189535f;
    const float PI2_HI  = 6.28318548202514648f;
    const float PI2_LO  = -1.7484555e-7f;
    float k = nearbyintf(theta * INV_2PI);
    float r = __fmaf_rn(-k, PI2_HI, theta);
    r = __fmaf_rn(-k, PI2_LO, r);
    sincosf(r, s, c);
}

// ======================= mma.sync fp16 GEMM (1 product) =======================
// C[M,N] = A[M,K] * B[N,K]^T ; both fp16.
// MODE 0: fp32 C.  MODE 5: fused projection epilogue (Q XPOS / K XPOS-inv / V^T)
template<int MODE>
__global__ void __launch_bounds__(TGN, 1)
tgemm(const __half* __restrict__ Ah, const __half* __restrict__ Bh,
      float* __restrict__ Cf,
      int M, int N, int K,
      long long sA, long long sB, long long sC)
{
    extern __shared__ char smem[];
    const uint32_t sb = smem_u32(smem);
    const int tid  = threadIdx.x;
    const int wid  = tid >> 5;
    const int lane = tid & 31;

    Ah += (long long)blockIdx.z * sA;
    Bh += (long long)blockIdx.z * sB;
    const int m0 = blockIdx.y * 128;
    const int n0 = blockIdx.x * 128;

    // warp layout: 2 (m) x 4 (n); warp tile 64(m) x 32(n)
    const int wm = (wid & 1) * 64;
    const int wn = (wid >> 1) * 32;

    float acc[16][4];
    #pragma unroll
    for (int i = 0; i < 16; i++)
        #pragma unroll
        for (int j = 0; j < 4; j++) acc[i][j] = 0.0f;

    const int rowA = wm + (lane & 15);
    const int chA  = lane >> 4;
    const int rowB = wn + (lane & 7) + ((lane & 16) >> 1);
    const int chB  = (lane >> 3) & 1;

    const int nk = K >> 6;          // k-tile = 64 halves (128B rows)

    const int cr  = tid >> 3;       // cp.async row helper
    const int cch = tid & 7;        // 16B chunk within 128B row

    auto issue = [&](int kt, int stg) {
        const uint32_t sbase = sb + (uint32_t)stg * STAGE_BYTES;
        #pragma unroll
        for (int p = 0; p < 4; p++) {
            int r = cr + p * 32;
            uint32_t d = sw128((uint32_t)(r * 128 + cch * 16));
            cpa16(sbase + d,         Ah + (size_t)(m0 + r) * K + kt * 64 + cch * 8);
            cpa16(sbase + OFF_B + d, Bh + (size_t)(n0 + r) * K + kt * 64 + cch * 8);
        }
        cp_commit();
    };

    // prologue: 4 stages in flight
    issue(0, 0); issue(1, 1); issue(2, 2); issue(3, 3);

    for (int it = 0; it < nk; ++it) {
        cp_wait<3>();
        __syncthreads();

        if (it + 4 < nk) issue(it + 4, (it + 4) % STAGES);
        else cp_commit();

        const uint32_t abase = sb + (uint32_t)((it % STAGES) * STAGE_BYTES);

        uint32_t Af[2][16], Bf[2][8];
        auto lda = [&](int ks, uint32_t* Ar) {
            #pragma unroll
            for (int mt = 0; mt < 4; mt++) {
                uint32_t off = sw128((uint32_t)((rowA + mt * 16) * 128 + ks * 32 + chA * 16));
                ldsm_x4(Ar + mt * 4, abase + off);
            }
        };
        auto ldb = [&](int ks, uint32_t* Br) {
            #pragma unroll
            for (int pr = 0; pr < 2; pr++) {
                uint32_t off = sw128((uint32_t)((rowB + pr * 16) * 128 + ks * 32 + chB * 16));
                ldsm_x4(Br + pr * 4, abase + OFF_B + off);
            }
        };

        lda(0, Af[0]); ldb(0, Bf[0]);
        #pragma unroll
        for (int ks = 0; ks < 4; ks++) {
            if (ks < 3) { lda(ks + 1, Af[(ks + 1) & 1]); ldb(ks + 1, Bf[(ks + 1) & 1]); }
            const uint32_t* a = Af[ks & 1];
            const uint32_t* b = Bf[ks & 1];
            #pragma unroll
            for (int mt = 0; mt < 4; mt++)
                #pragma unroll
                for (int nt = 0; nt < 4; nt++) {
                    const int bi = (nt >> 1) * 4 + (nt & 1) * 2;
                    mma_f16(acc[mt * 4 + nt], a + mt * 4, b[bi], b[bi + 1]);
                }
        }
    }

    // ======================= epilogue =======================
    if (MODE == 0) {
        float* Cb = Cf + (long long)blockIdx.z * sC;
        #pragma unroll
        for (int mt = 0; mt < 4; mt++) {
            const int r = m0 + wm + mt * 16 + (lane >> 2);
            #pragma unroll
            for (int nt = 0; nt < 4; nt++) {
                const int cc = n0 + wn + nt * 8 + (lane & 3) * 2;
                float* c = acc[mt * 4 + nt];
                *(float2*)(Cb + (size_t)r * N + cc)       = make_float2(c[0], c[1]);
                *(float2*)(Cb + (size_t)(r + 8) * N + cc) = make_float2(c[2], c[3]);
            }
        }
    } else {
        const int seg = n0 >> 10;    // 0 = Q, 1 = K, 2 = V
        if (seg < 2) {
            __half* Co = seg ? g_Kh : g_Qh;
            const float LN1E4 = 9.210340371976184f;
            #pragma unroll
            for (int nt = 0; nt < 4; nt++) {
                const int cc = n0 + wn + nt * 8 + (lane & 3) * 2;
                const int ncol = cc & 1023;
                const int jj = ncol >> 1;
                float lgsv = logf((2.0f * (float)jj + 0.4f * 1024.0f) / (1.4f * 1024.0f));
                if (seg == 1) lgsv = -lgsv;
                const float invf = expf(-(float)jj * (2.0f / 1024.0f) * LN1E4);
                #pragma unroll
                for (int mt = 0; mt < 4; mt++) {
                    float* c = acc[mt * 4 + nt];
                    #pragma unroll
                    for (int h = 0; h < 2; h++) {
                        const int row = m0 + wm + mt * 16 + (lane >> 2) + h * 8;
                        const int l = row & (LL - 1);
                        const float lf = (float)l;
                        float scale = expf(lf * (1.0f / 512.0f) * lgsv);
                        float s, co;
                        sincos_red(lf * invf, &s, &co);
                        s *= scale; co *= scale;
                        float xe = c[2 * h], xo = c[2 * h + 1];
                        *(__half2*)(Co + (size_t)row * DH + ncol) =
                            __halves2half2(__float2half_rn(xe * co - xo * s),
                                           __float2half_rn(xo * co + xe * s));
                    }
                }
            }
        } else {
            #pragma unroll
            for (int mt = 0; mt < 4; mt++) {
                const int m = m0 + wm + mt * 16 + (lane >> 2);
                const int b = m >> 11;
                const int l = m & (LL - 1);
                __half* base = g_Vth + (size_t)b * DH * LL;
                #pragma unroll
                for (int nt = 0; nt < 4; nt++) {
                    const int cc = n0 + wn + nt * 8 + (lane & 3) * 2;
                    const int dh = cc - 2048;
                    float* c = acc[mt * 4 + nt];
                    base[(size_t)dh * LL + l]           = __float2half_rn(c[0]);
                    base[(size_t)(dh + 1) * LL + l]     = __float2half_rn(c[1]);
                    base[(size_t)dh * LL + l + 8]       = __float2half_rn(c[2]);
                    base[(size_t)(dh + 1) * LL + l + 8] = __float2half_rn(c[3]);
                }
            }
        }
    }
}

// ======================= X round (fp32 -> fp16) =======================
__global__ void round_x(const float* __restrict__ in, __half* __restrict__ oh, int n4)
{
    int i = blockIdx.x * blockDim.x + threadIdx.x;
    if (i >= n4) return;
    float4 v = ((const float4*)in)[i];
    ((__half2*)oh)[2 * i]     = __floats2half2_rn(v.x, v.y);
    ((__half2*)oh)[2 * i + 1] = __floats2half2_rn(v.z, v.w);
}

// ======================= weight transpose + fp16 round =======================
__global__ void transpose_h(const float* __restrict__ in, __half* __restrict__ out) {
    __shared__ float t[32][33];
    const int bx = blockIdx.x * 32, by = blockIdx.y * 32;
    #pragma unroll
    for (int i = threadIdx.y; i < 32; i += 8)
        t[i][threadIdx.x] = in[(size_t)(by + i) * DH + bx + threadIdx.x];
    __syncthreads();
    #pragma unroll
    for (int i = threadIdx.y; i < 32; i += 8)
        out[(size_t)(bx + i) * HH + by + threadIdx.x] =
            __float2half_rn(t[threadIdx.x][i]);
}

// ======================= softmax * D -> fp16 =======================
__global__ void softmax_d_kernel(const float* __restrict__ S, __half* __restrict__ Ph)
{
    const int q = blockIdx.x;
    const size_t ro = ((size_t)blockIdx.y * LL + q) * (size_t)LL;
    const float* row = S + ro;
    const int tid = threadIdx.x;
    const int lane = tid & 31;
    const int warp = tid >> 5;
    const float LN_GAMMA = -0.10536051565782628f;  // ln(0.9)

    __shared__ float red[8];

    float v[8];
    float m = -INFINITY;
    #pragma unroll
    for (int i = 0; i < 8; i++) {
        v[i] = row[i * 256 + tid];
        m = fmaxf(m, v[i]);
    }
    #pragma unroll
    for (int o = 16; o > 0; o >>= 1)
        m = fmaxf(m, __shfl_xor_sync(0xffffffffu, m, o));
    if (lane == 0) red[warp] = m;
    __syncthreads();
    float mb = red[0];
    #pragma unroll
    for (int w = 1; w < 8; w++) mb = fmaxf(mb, red[w]);
    __syncthreads();

    float sum = 0.0f;
    #pragma unroll
    for (int i = 0; i < 8; i++) {
        v[i] = expf(v[i] - mb);
        sum += v[i];
    }
    #pragma unroll
    for (int o = 16; o > 0; o >>= 1)
        sum += __shfl_xor_sync(0xffffffffu, sum, o);
    if (lane == 0) red[warp] = sum;
    __syncthreads();
    float tot = 0.0f;
    #pragma unroll
    for (int w = 0; w < 8; w++) tot += red[w];
    float inv = 1.0f / tot;

    #pragma unroll
    for (int i = 0; i < 8; i++) {
        int k = i * 256 + tid;
        float d = expf(fabsf((float)(q - k)) * LN_GAMMA);
        Ph[ro + k] = __float2half_rn(v[i] * d * inv);
    }
}

// ======================= launcher =======================
extern "C" void kernel_launch(void* const* d_in, const int* in_sizes, int n_in,
                              void* d_out, int out_size)
{
    const float* X  = (const float*)d_in[0];
    const float* WQ = (const float*)d_in[1];
    const float* WK = (const float*)d_in[2];
    const float* WV = (const float*)d_in[3];
    float* out = (float*)d_out;

    __half *Xh, *Wt, *Qh, *Kh, *Vth, *Ph;
    float* S;
    cudaGetSymbolAddress((void**)&Xh,  g_Xh);
    cudaGetSymbolAddress((void**)&Wt,  g_Wt);
    cudaGetSymbolAddress((void**)&Qh,  g_Qh);
    cudaGetSymbolAddress((void**)&Kh,  g_Kh);
    cudaGetSymbolAddress((void**)&Vth, g_Vth);
    cudaGetSymbolAddress((void**)&S,   g_S);
    cudaGetSymbolAddress((void**)&Ph,  g_Ph);

    cudaFuncSetAttribute(tgemm<0>, cudaFuncAttributeMaxDynamicSharedMemorySize, SMEM_TOTAL);
    cudaFuncSetAttribute(tgemm<5>, cudaFuncAttributeMaxDynamicSharedMemorySize, SMEM_TOTAL);

    const int M = BB * LL;  // 16384

    // 0) operand preparation
    int n4 = M * HH / 4;
    round_x<<<(n4 + 255) / 256, 256>>>(X, Xh, n4);
    dim3 tb(32, 8), tg(32, 32);
    transpose_h<<<tg, tb>>>(WQ, Wt);
    transpose_h<<<tg, tb>>>(WK, Wt + (size_t)HH * DH);
    transpose_h<<<tg, tb>>>(WV, Wt + (size_t)2 * HH * DH);

    // 1) fused QKV projection (N = 3072): Q XPOS, K XPOS-inv, V transposed
    dim3 g1(3 * DH / 128, M / 128, 1);
    tgemm<5><<<g1, TGN, SMEM_TOTAL>>>(Xh, Wt, nullptr, M, 3 * DH, HH, 0, 0, 0);

    // 2) scores = Q K^T per batch -> fp32 S
    dim3 g2(LL / 128, LL / 128, BB);
    tgemm<0><<<g2, TGN, SMEM_TOTAL>>>(Qh, Kh, S, LL, LL, DH,
                                      (long long)LL * DH, (long long)LL * DH,
                                      (long long)LL * LL);

    // 3) softmax * D -> fp16 P
    softmax_d_kernel<<<dim3(LL, BB), 256>>>(S, Ph);

    // 4) out = P V per batch (B = V^T fp16, [Dh][L] K-major)
    dim3 g4(DH / 128, LL / 128, BB);
    tgemm<0><<<g4, TGN, SMEM_TOTAL>>>(Ph, Vth, out, LL, DH, LL,
                                      (long long)LL * LL, (long long)DH * LL,
                                      (long long)LL * DH);
}

// round 6
// speedup vs baseline: 7.4901x; 1.1939x over previous
#include <cuda_runtime.h>
#include <cuda_fp16.h>
#include <math.h>
#include <stdint.h>

// Problem constants (fixed by setup_inputs)
#define BB  8
#define LL  2048
#define HH  1024
#define DH  1024

#define TGN 256          // 8 warps per CTA
#define STAGES 5
#define OFF_B   16384
#define STAGE_BYTES 32768
#define SMEM_TOTAL (STAGES * STAGE_BYTES)   // 160 KB

#define BAND_T 2         // band half-width in 128-tiles (cutoff gamma^257 ~ 2e-12)

// ---- scratch (static device globals; allocation-free) ----
__device__ __half g_Xh [(size_t)BB * LL * HH];
__device__ __half g_Wt [(size_t)3 * HH * DH];   // WQ^T | WK^T | WV^T
__device__ __half g_Qh [(size_t)BB * LL * DH];
__device__ __half g_Kh [(size_t)BB * LL * DH];
__device__ __half g_Vth[(size_t)BB * LL * DH];  // V^T per batch: [Dh][L]
__device__ float  g_S  [(size_t)BB * LL * LL];  // banded use only
__device__ __half g_Ph [(size_t)BB * LL * LL];  // banded use only
__device__ float2 g_part[(size_t)BB * LL * 64]; // per-row per-32col (max, sumexp)

// ======================= helpers =======================
__device__ __forceinline__ uint32_t smem_u32(const void* p) {
    uint32_t a;
    asm("{ .reg .u64 t; cvta.to.shared.u64 t, %1; cvt.u32.u64 %0, t; }" : "=r"(a) : "l"(p));
    return a;
}
__device__ __forceinline__ uint32_t sw128(uint32_t off) {
    return off ^ ((off >> 3) & 0x70);
}
__device__ __forceinline__ void cpa16(uint32_t dst, const void* src) {
    asm volatile("cp.async.cg.shared.global [%0], [%1], 16;" :: "r"(dst), "l"(src));
}
__device__ __forceinline__ void cp_commit() {
    asm volatile("cp.async.commit_group;" ::: "memory");
}
template<int N> __device__ __forceinline__ void cp_wait() {
    asm volatile("cp.async.wait_group %0;" :: "n"(N) : "memory");
}
__device__ __forceinline__ void ldsm_x4(uint32_t* r, uint32_t addr) {
    asm volatile("ldmatrix.sync.aligned.m8n8.x4.shared.b16 {%0,%1,%2,%3}, [%4];"
                 : "=r"(r[0]), "=r"(r[1]), "=r"(r[2]), "=r"(r[3]) : "r"(addr));
}
__device__ __forceinline__ void mma_f16(float* c, const uint32_t* a,
                                        uint32_t b0, uint32_t b1) {
    asm volatile(
        "mma.sync.aligned.m16n8k16.row.col.f32.f16.f16.f32 "
        "{%0,%1,%2,%3}, {%4,%5,%6,%7}, {%8,%9}, {%0,%1,%2,%3};"
        : "+f"(c[0]), "+f"(c[1]), "+f"(c[2]), "+f"(c[3])
        : "r"(a[0]), "r"(a[1]), "r"(a[2]), "r"(a[3]), "r"(b0), "r"(b1));
}

// Cody-Waite reduced sincos (survives --use_fast_math; theta in [0, ~2100))
__device__ __forceinline__ void sincos_red(float theta, float* s, float* c) {
    const float INV_2PI = 0.15915494309189535f;
    const float PI2_HI  = 6.28318548202514648f;
    const float PI2_LO  = -1.7484555e-7f;
    float k = nearbyintf(theta * INV_2PI);
    float r = __fmaf_rn(-k, PI2_HI, theta);
    r = __fmaf_rn(-k, PI2_LO, r);
    sincosf(r, s, c);
}

// ======================= mma.sync fp16 GEMM =======================
// C[M,N] = A[M,K] * B[N,K]^T ; both fp16.
// MODE 5: fused QKV projection epilogue (Q XPOS / K XPOS-inv / V^T)
// MODE 6: scores -> banded S + per-subtile (max, sumexp) partials
// MODE 7: banded P*V -> fp32 out
template<int MODE>
__global__ void __launch_bounds__(TGN, 1)
tgemm(const __half* __restrict__ Ah, const __half* __restrict__ Bh,
      float* __restrict__ Cf,
      int M, int N, int K,
      long long sA, long long sB, long long sC)
{
    extern __shared__ char smem[];
    const uint32_t sb = smem_u32(smem);
    const int tid  = threadIdx.x;
    const int wid  = tid >> 5;
    const int lane = tid & 31;

    Ah += (long long)blockIdx.z * sA;
    Bh += (long long)blockIdx.z * sB;
    const int m0 = blockIdx.y * 128;
    const int n0 = blockIdx.x * 128;

    // warp layout: 2 (m) x 4 (n); warp tile 64(m) x 32(n)
    const int wm = (wid & 1) * 64;
    const int wn = (wid >> 1) * 32;

    float acc[16][4];
    #pragma unroll
    for (int i = 0; i < 16; i++)
        #pragma unroll
        for (int j = 0; j < 4; j++) acc[i][j] = 0.0f;

    const int rowA = wm + (lane & 15);
    const int chA  = lane >> 4;
    const int rowB = wn + (lane & 7) + ((lane & 16) >> 1);
    const int chB  = (lane >> 3) & 1;

    // k64-tile range (banded for MODE 7)
    int ktlo = 0, k64n = K >> 6;
    if (MODE == 7) {
        const int qt = (int)blockIdx.y;
        const int t0 = max(0, qt - BAND_T);
        const int t1 = min(K >> 7, qt + BAND_T + 1);
        ktlo = t0 << 1;
        k64n = (t1 - t0) << 1;       // always >= 6
    }

    const int cr  = tid >> 3;
    const int cch = tid & 7;

    auto issue = [&](int kt, int stg) {
        const uint32_t sbase = sb + (uint32_t)stg * STAGE_BYTES;
        #pragma unroll
        for (int p = 0; p < 4; p++) {
            int r = cr + p * 32;
            uint32_t d = sw128((uint32_t)(r * 128 + cch * 16));
            cpa16(sbase + d,         Ah + (size_t)(m0 + r) * K + kt * 64 + cch * 8);
            cpa16(sbase + OFF_B + d, Bh + (size_t)(n0 + r) * K + kt * 64 + cch * 8);
        }
        cp_commit();
    };

    issue(ktlo, 0); issue(ktlo + 1, 1); issue(ktlo + 2, 2); issue(ktlo + 3, 3);

    for (int it = 0; it < k64n; ++it) {
        cp_wait<3>();
        __syncthreads();

        if (it + 4 < k64n) issue(ktlo + it + 4, (it + 4) % STAGES);
        else cp_commit();

        const uint32_t abase = sb + (uint32_t)((it % STAGES) * STAGE_BYTES);

        uint32_t Af[2][16], Bf[2][8];
        auto lda = [&](int ks, uint32_t* Ar) {
            #pragma unroll
            for (int mt = 0; mt < 4; mt++) {
                uint32_t off = sw128((uint32_t)((rowA + mt * 16) * 128 + ks * 32 + chA * 16));
                ldsm_x4(Ar + mt * 4, abase + off);
            }
        };
        auto ldb = [&](int ks, uint32_t* Br) {
            #pragma unroll
            for (int pr = 0; pr < 2; pr++) {
                uint32_t off = sw128((uint32_t)((rowB + pr * 16) * 128 + ks * 32 + chB * 16));
                ldsm_x4(Br + pr * 4, abase + OFF_B + off);
            }
        };

        lda(0, Af[0]); ldb(0, Bf[0]);
        #pragma unroll
        for (int ks = 0; ks < 4; ks++) {
            if (ks < 3) { lda(ks + 1, Af[(ks + 1) & 1]); ldb(ks + 1, Bf[(ks + 1) & 1]); }
            const uint32_t* a = Af[ks & 1];
            const uint32_t* b = Bf[ks & 1];
            #pragma unroll
            for (int mt = 0; mt < 4; mt++)
                #pragma unroll
                for (int nt = 0; nt < 4; nt++) {
                    const int bi = (nt >> 1) * 4 + (nt & 1) * 2;
                    mma_f16(acc[mt * 4 + nt], a + mt * 4, b[bi], b[bi + 1]);
                }
        }
    }

    // ======================= epilogue =======================
    if (MODE == 7) {
        float* Cb = Cf + (long long)blockIdx.z * sC;
        #pragma unroll
        for (int mt = 0; mt < 4; mt++) {
            const int r = m0 + wm + mt * 16 + (lane >> 2);
            #pragma unroll
            for (int nt = 0; nt < 4; nt++) {
                const int cc = n0 + wn + nt * 8 + (lane & 3) * 2;
                float* c = acc[mt * 4 + nt];
                *(float2*)(Cb + (size_t)r * N + cc)       = make_float2(c[0], c[1]);
                *(float2*)(Cb + (size_t)(r + 8) * N + cc) = make_float2(c[2], c[3]);
            }
        }
    } else if (MODE == 6) {
        const int qt = m0 >> 7;
        const int kt = n0 >> 7;
        const bool sband = (kt >= qt - BAND_T) && (kt <= qt + BAND_T);
        float* Sb = Cf + (long long)blockIdx.z * sC;
        const int subt = (n0 + wn) >> 5;    // 32-col subtile index (0..63)
        const size_t prow0 = (size_t)(blockIdx.z * LL) * 64;
        #pragma unroll
        for (int mt = 0; mt < 4; mt++) {
            #pragma unroll
            for (int h = 0; h < 2; h++) {
                const int row = m0 + wm + mt * 16 + (lane >> 2) + h * 8;
                float v[8];
                #pragma unroll
                for (int nt = 0; nt < 4; nt++) {
                    v[2 * nt]     = acc[mt * 4 + nt][2 * h];
                    v[2 * nt + 1] = acc[mt * 4 + nt][2 * h + 1];
                }
                float mx = v[0];
                #pragma unroll
                for (int i = 1; i < 8; i++) mx = fmaxf(mx, v[i]);
                mx = fmaxf(mx, __shfl_xor_sync(0xffffffffu, mx, 1));
                mx = fmaxf(mx, __shfl_xor_sync(0xffffffffu, mx, 2));
                float se = 0.0f;
                #pragma unroll
                for (int i = 0; i < 8; i++) se += expf(v[i] - mx);
                se += __shfl_xor_sync(0xffffffffu, se, 1);
                se += __shfl_xor_sync(0xffffffffu, se, 2);
                if ((lane & 3) == 0)
                    g_part[prow0 + (size_t)row * 64 + subt] = make_float2(mx, se);
                if (sband) {
                    const int cc = n0 + wn + (lane & 3) * 2;
                    float* sp = Sb + (size_t)row * N + cc;
                    #pragma unroll
                    for (int nt = 0; nt < 4; nt++)
                        *(float2*)(sp + nt * 8) = make_float2(v[2 * nt], v[2 * nt + 1]);
                }
            }
        }
    } else {
        // MODE 5: fused QKV projection
        const int seg = n0 >> 10;    // 0 = Q, 1 = K, 2 = V
        if (seg < 2) {
            __half* Co = seg ? g_Kh : g_Qh;
            const float LN1E4 = 9.210340371976184f;
            #pragma unroll
            for (int nt = 0; nt < 4; nt++) {
                const int cc = n0 + wn + nt * 8 + (lane & 3) * 2;
                const int ncol = cc & 1023;
                const int jj = ncol >> 1;
                float lgsv = logf((2.0f * (float)jj + 0.4f * 1024.0f) / (1.4f * 1024.0f));
                if (seg == 1) lgsv = -lgsv;
                const float invf = expf(-(float)jj * (2.0f / 1024.0f) * LN1E4);
                #pragma unroll
                for (int mt = 0; mt < 4; mt++) {
                    float* c = acc[mt * 4 + nt];
                    #pragma unroll
                    for (int h = 0; h < 2; h++) {
                        const int row = m0 + wm + mt * 16 + (lane >> 2) + h * 8;
                        const int l = row & (LL - 1);
                        const float lf = (float)l;
                        float scale = expf(lf * (1.0f / 512.0f) * lgsv);
                        float s, co;
                        sincos_red(lf * invf, &s, &co);
                        s *= scale; co *= scale;
                        float xe = c[2 * h], xo = c[2 * h + 1];
                        *(__half2*)(Co + (size_t)row * DH + ncol) =
                            __halves2half2(__float2half_rn(xe * co - xo * s),
                                           __float2half_rn(xo * co + xe * s));
                    }
                }
            }
        } else {
            #pragma unroll
            for (int mt = 0; mt < 4; mt++) {
                const int m = m0 + wm + mt * 16 + (lane >> 2);
                const int b = m >> 11;
                const int l = m & (LL - 1);
                __half* base = g_Vth + (size_t)b * DH * LL;
                #pragma unroll
                for (int nt = 0; nt < 4; nt++) {
                    const int cc = n0 + wn + nt * 8 + (lane & 3) * 2;
                    const int dh = cc - 2048;
                    float* c = acc[mt * 4 + nt];
                    base[(size_t)dh * LL + l]           = __float2half_rn(c[0]);
                    base[(size_t)(dh + 1) * LL + l]     = __float2half_rn(c[1]);
                    base[(size_t)dh * LL + l + 8]       = __float2half_rn(c[2]);
                    base[(size_t)(dh + 1) * LL + l + 8] = __float2half_rn(c[3]);
                }
            }
        }
    }
}

// ======================= X round (fp32 -> fp16) =======================
__global__ void round_x(const float* __restrict__ in, __half* __restrict__ oh, int n4)
{
    int i = blockIdx.x * blockDim.x + threadIdx.x;
    if (i >= n4) return;
    float4 v = ((const float4*)in)[i];
    ((__half2*)oh)[2 * i]     = __floats2half2_rn(v.x, v.y);
    ((__half2*)oh)[2 * i + 1] = __floats2half2_rn(v.z, v.w);
}

// ======================= weight transpose + fp16 round =======================
__global__ void transpose_h(const float* __restrict__ in, __half* __restrict__ out) {
    __shared__ float t[32][33];
    const int bx = blockIdx.x * 32, by = blockIdx.y * 32;
    #pragma unroll
    for (int i = threadIdx.y; i < 32; i += 8)
        t[i][threadIdx.x] = in[(size_t)(by + i) * DH + bx + threadIdx.x];
    __syncthreads();
    #pragma unroll
    for (int i = threadIdx.y; i < 32; i += 8)
        out[(size_t)(bx + i) * HH + by + threadIdx.x] =
            __float2half_rn(t[threadIdx.x][i]);
}

// ======================= combine partials + banded P production =======================
__global__ void __launch_bounds__(128, 8)
pk_kernel(const float* __restrict__ S, const float2* __restrict__ part,
          __half* __restrict__ Ph)
{
    const int q = blockIdx.x;
    const int b = blockIdx.y;
    const size_t rbase = (size_t)(b * LL + q);
    const float2* pp = part + rbase * 64;
    const int tid = threadIdx.x;
    const int lane = tid & 31;
    const int warp = tid >> 5;
    const float LN_GAMMA = -0.10536051565782628f;

    __shared__ float redm[4], redz[4];

    float2 pv = (tid < 64) ? pp[tid] : make_float2(-1e30f, 0.0f);
    float m = pv.x;
    #pragma unroll
    for (int o = 16; o > 0; o >>= 1)
        m = fmaxf(m, __shfl_xor_sync(0xffffffffu, m, o));
    if (lane == 0) redm[warp] = m;
    __syncthreads();
    m = fmaxf(fmaxf(redm[0], redm[1]), fmaxf(redm[2], redm[3]));

    float z = pv.y * expf(pv.x - m);
    #pragma unroll
    for (int o = 16; o > 0; o >>= 1)
        z += __shfl_xor_sync(0xffffffffu, z, o);
    if (lane == 0) redz[warp] = z;
    __syncthreads();
    const float invZ = 1.0f / (redz[0] + redz[1] + redz[2] + redz[3]);

    const int qt = q >> 7;
    const int klo = max(0, qt - BAND_T) * 128;
    const int khi = min(16, qt + BAND_T + 1) * 128;
    const float* Sr = S + rbase * LL;
    __half* Pr = Ph + rbase * LL;
    for (int k = klo + tid; k < khi; k += 128) {
        float d = expf(fabsf((float)(q - k)) * LN_GAMMA);
        Pr[k] = __float2half_rn(expf(Sr[k] - m) * d * invZ);
    }
}

// ======================= launcher =======================
extern "C" void kernel_launch(void* const* d_in, const int* in_sizes, int n_in,
                              void* d_out, int out_size)
{
    const float* X  = (const float*)d_in[0];
    const float* WQ = (const float*)d_in[1];
    const float* WK = (const float*)d_in[2];
    const float* WV = (const float*)d_in[3];
    float* out = (float*)d_out;

    __half *Xh, *Wt, *Qh, *Kh, *Vth, *Ph;
    float* S;
    float2* Pt;
    cudaGetSymbolAddress((void**)&Xh,  g_Xh);
    cudaGetSymbolAddress((void**)&Wt,  g_Wt);
    cudaGetSymbolAddress((void**)&Qh,  g_Qh);
    cudaGetSymbolAddress((void**)&Kh,  g_Kh);
    cudaGetSymbolAddress((void**)&Vth, g_Vth);
    cudaGetSymbolAddress((void**)&S,   g_S);
    cudaGetSymbolAddress((void**)&Ph,  g_Ph);
    cudaGetSymbolAddress((void**)&Pt,  g_part);

    cudaFuncSetAttribute(tgemm<5>, cudaFuncAttributeMaxDynamicSharedMemorySize, SMEM_TOTAL);
    cudaFuncSetAttribute(tgemm<6>, cudaFuncAttributeMaxDynamicSharedMemorySize, SMEM_TOTAL);
    cudaFuncSetAttribute(tgemm<7>, cudaFuncAttributeMaxDynamicSharedMemorySize, SMEM_TOTAL);

    const int M = BB * LL;  // 16384

    // 0) operand preparation
    int n4 = M * HH / 4;
    round_x<<<(n4 + 255) / 256, 256>>>(X, Xh, n4);
    dim3 tb(32, 8), tg(32, 32);
    transpose_h<<<tg, tb>>>(WQ, Wt);
    transpose_h<<<tg, tb>>>(WK, Wt + (size_t)HH * DH);
    transpose_h<<<tg, tb>>>(WV, Wt + (size_t)2 * HH * DH);

    // 1) fused QKV projection
    dim3 g1(3 * DH / 128, M / 128, 1);
    tgemm<5><<<g1, TGN, SMEM_TOTAL>>>(Xh, Wt, nullptr, M, 3 * DH, HH, 0, 0, 0);

    // 2) scores = Q K^T per batch -> banded S + softmax partials
    dim3 g2(LL / 128, LL / 128, BB);
    tgemm<6><<<g2, TGN, SMEM_TOTAL>>>(Qh, Kh, S, LL, LL, DH,
                                      (long long)LL * DH, (long long)LL * DH,
                                      (long long)LL * LL);

    // 3) combine partials + banded P = softmax * D (fp16)
    pk_kernel<<<dim3(LL, BB), 128>>>(S, Pt, Ph);

    // 4) out = P V per batch, banded k-loop
    dim3 g4(DH / 128, LL / 128, BB);
    tgemm<7><<<g4, TGN, SMEM_TOTAL>>>(Ph, Vth, out, LL, DH, LL,
                                      (long long)LL * LL, (long long)DH * LL,
                                      (long long)LL * DH);
}

// round 7
// speedup vs baseline: 7.9927x; 1.0671x over previous
#include <cuda_runtime.h>
#include <cuda_fp16.h>
#include <math.h>
#include <stdint.h>

// Problem constants (fixed by setup_inputs)
#define BB  8
#define LL  2048
#define HH  1024
#define DH  1024

#define TGN 256          // 8 warps per CTA
#define STAGES 4
#define OFF_B   32768    // A tile 256x64 fp16 = 32KB
#define STAGE_BYTES 49152
#define SMEM_TOTAL (STAGES * STAGE_BYTES)   // 192 KB

#define BAND_T 2         // band half-width in 128-tiles (cutoff ~gamma^257)

// ---- scratch (static device globals; allocation-free) ----
__device__ __half g_Xh [(size_t)BB * LL * HH];
__device__ __half g_Wt [(size_t)3 * HH * DH];   // WQ^T | WK^T | WV^T
__device__ __half g_Qh [(size_t)BB * LL * DH];
__device__ __half g_Kh [(size_t)BB * LL * DH];
__device__ __half g_Vth[(size_t)BB * LL * DH];  // V^T per batch: [Dh][L]
__device__ float  g_S  [(size_t)BB * LL * LL];  // banded use only
__device__ __half g_Ph [(size_t)BB * LL * LL];  // banded use only
__device__ float2 g_part[(size_t)BB * LL * 64]; // per-row per-32col (max, sumexp)

// ======================= helpers =======================
__device__ __forceinline__ uint32_t smem_u32(const void* p) {
    uint32_t a;
    asm("{ .reg .u64 t; cvta.to.shared.u64 t, %1; cvt.u32.u64 %0, t; }" : "=r"(a) : "l"(p));
    return a;
}
__device__ __forceinline__ uint32_t sw128(uint32_t off) {
    return off ^ ((off >> 3) & 0x70);
}
__device__ __forceinline__ void cpa16(uint32_t dst, const void* src) {
    asm volatile("cp.async.cg.shared.global [%0], [%1], 16;" :: "r"(dst), "l"(src));
}
__device__ __forceinline__ void cp_commit() {
    asm volatile("cp.async.commit_group;" ::: "memory");
}
template<int N> __device__ __forceinline__ void cp_wait() {
    asm volatile("cp.async.wait_group %0;" :: "n"(N) : "memory");
}
__device__ __forceinline__ void ldsm_x4(uint32_t* r, uint32_t addr) {
    asm volatile("ldmatrix.sync.aligned.m8n8.x4.shared.b16 {%0,%1,%2,%3}, [%4];"
                 : "=r"(r[0]), "=r"(r[1]), "=r"(r[2]), "=r"(r[3]) : "r"(addr));
}
__device__ __forceinline__ void mma_f16(float* c, const uint32_t* a,
                                        uint32_t b0, uint32_t b1) {
    asm volatile(
        "mma.sync.aligned.m16n8k16.row.col.f32.f16.f16.f32 "
        "{%0,%1,%2,%3}, {%4,%5,%6,%7}, {%8,%9}, {%0,%1,%2,%3};"
        : "+f"(c[0]), "+f"(c[1]), "+f"(c[2]), "+f"(c[3])
        : "r"(a[0]), "r"(a[1]), "r"(a[2]), "r"(a[3]), "r"(b0), "r"(b1));
}

// Cody-Waite reduced sincos (survives --use_fast_math; theta in [0, ~2100))
__device__ __forceinline__ void sincos_red(float theta, float* s, float* c) {
    const float INV_2PI = 0.15915494309189535f;
    const float PI2_HI  = 6.28318548202514648f;
    const float PI2_LO  = -1.7484555e-7f;
    float k = nearbyintf(theta * INV_2PI);
    float r = __fmaf_rn(-k, PI2_HI, theta);
    r = __fmaf_rn(-k, PI2_LO, r);
    sincosf(r, s, c);
}

// ======================= mma.sync fp16 GEMM, 256x128 CTA tile =======================
// C[M,N] = A[M,K] * B[N,K]^T ; both fp16. Warp layout 4m x 2n, warptile 64x64.
// MODE 5: fused QKV projection epilogue (Q XPOS / K XPOS-inv / V^T)
// MODE 6: scores -> banded S + per-subtile (max, sumexp) partials
// MODE 7: banded P*V -> fp32 out
template<int MODE>
__global__ void __launch_bounds__(TGN, 1)
tgemm(const __half* __restrict__ Ah, const __half* __restrict__ Bh,
      float* __restrict__ Cf,
      int M, int N, int K,
      long long sA, long long sB, long long sC)
{
    extern __shared__ char smem[];
    const uint32_t sb = smem_u32(smem);
    const int tid  = threadIdx.x;
    const int wid  = tid >> 5;
    const int lane = tid & 31;

    Ah += (long long)blockIdx.z * sA;
    Bh += (long long)blockIdx.z * sB;
    const int m0 = blockIdx.y * 256;
    const int n0 = blockIdx.x * 128;

    // warp layout: 4 (m) x 2 (n); warp tile 64(m) x 64(n)
    const int wm = (wid & 3) * 64;
    const int wn = (wid >> 2) * 64;

    float acc[32][4];
    #pragma unroll
    for (int i = 0; i < 32; i++)
        #pragma unroll
        for (int j = 0; j < 4; j++) acc[i][j] = 0.0f;

    const int rowA = wm + (lane & 15);
    const int chA  = lane >> 4;
    const int rowB = wn + (lane & 7) + ((lane & 16) >> 1);
    const int chB  = (lane >> 3) & 1;

    // k64-tile range (banded for MODE 7)
    int ktlo = 0, k64n = K >> 6;
    if (MODE == 7) {
        const int g = (int)blockIdx.y;          // 256-row group
        const int t0 = max(0, 2 * g - BAND_T);
        const int t1 = min(K >> 7, 2 * g + 2 + BAND_T);
        ktlo = t0 << 1;
        k64n = (t1 - t0) << 1;                  // 8..12
    }

    const int cr  = tid >> 3;       // 0..31
    const int cch = tid & 7;

    auto issue = [&](int kt, int stg) {
        const uint32_t sbase = sb + (uint32_t)stg * STAGE_BYTES;
        #pragma unroll
        for (int p = 0; p < 8; p++) {           // A: 256 rows
            int r = cr + p * 32;
            uint32_t d = sw128((uint32_t)(r * 128 + cch * 16));
            cpa16(sbase + d, Ah + (size_t)(m0 + r) * K + kt * 64 + cch * 8);
        }
        #pragma unroll
        for (int p = 0; p < 4; p++) {           // B: 128 rows
            int r = cr + p * 32;
            uint32_t d = sw128((uint32_t)(r * 128 + cch * 16));
            cpa16(sbase + OFF_B + d, Bh + (size_t)(n0 + r) * K + kt * 64 + cch * 8);
        }
        cp_commit();
    };

    issue(ktlo, 0); issue(ktlo + 1, 1); issue(ktlo + 2, 2);

    for (int it = 0; it < k64n; ++it) {
        cp_wait<2>();
        __syncthreads();

        if (it + 3 < k64n) issue(ktlo + it + 3, (it + 3) & 3);
        else cp_commit();

        const uint32_t abase = sb + (uint32_t)((it & 3) * STAGE_BYTES);

        uint32_t Af[2][16], Bf[2][16];
        auto lda = [&](int ks, uint32_t* Ar) {
            #pragma unroll
            for (int mt = 0; mt < 4; mt++) {
                uint32_t off = sw128((uint32_t)((rowA + mt * 16) * 128 + ks * 32 + chA * 16));
                ldsm_x4(Ar + mt * 4, abase + off);
            }
        };
        auto ldb = [&](int ks, uint32_t* Br) {
            #pragma unroll
            for (int pr = 0; pr < 4; pr++) {
                uint32_t off = sw128((uint32_t)((rowB + pr * 16) * 128 + ks * 32 + chB * 16));
                ldsm_x4(Br + pr * 4, abase + OFF_B + off);
            }
        };

        lda(0, Af[0]); ldb(0, Bf[0]);
        #pragma unroll
        for (int ks = 0; ks < 4; ks++) {
            if (ks < 3) { lda(ks + 1, Af[(ks + 1) & 1]); ldb(ks + 1, Bf[(ks + 1) & 1]); }
            const uint32_t* a = Af[ks & 1];
            const uint32_t* b = Bf[ks & 1];
            #pragma unroll
            for (int mt = 0; mt < 4; mt++)
                #pragma unroll
                for (int nt = 0; nt < 8; nt++) {
                    const int bi = (nt >> 1) * 4 + (nt & 1) * 2;
                    mma_f16(acc[mt * 8 + nt], a + mt * 4, b[bi], b[bi + 1]);
                }
        }
    }

    // ======================= epilogue =======================
    if (MODE == 7) {
        float* Cb = Cf + (long long)blockIdx.z * sC;
        #pragma unroll
        for (int mt = 0; mt < 4; mt++) {
            const int r = m0 + wm + mt * 16 + (lane >> 2);
            #pragma unroll
            for (int nt = 0; nt < 8; nt++) {
                const int cc = n0 + wn + nt * 8 + (lane & 3) * 2;
                float* c = acc[mt * 8 + nt];
                *(float2*)(Cb + (size_t)r * N + cc)       = make_float2(c[0], c[1]);
                *(float2*)(Cb + (size_t)(r + 8) * N + cc) = make_float2(c[2], c[3]);
            }
        }
    } else if (MODE == 6) {
        const int g  = m0 >> 8;                 // 256-row group
        const int kt = n0 >> 7;
        const bool sband = (kt >= 2 * g - BAND_T) && (kt < 2 * g + 2 + BAND_T);
        float* Sb = Cf + (long long)blockIdx.z * sC;
        const size_t prow0 = (size_t)(blockIdx.z * LL) * 64;
        const int subt0 = (n0 + wn) >> 5;       // first 32-col subtile of this warp
        #pragma unroll
        for (int mt = 0; mt < 4; mt++) {
            #pragma unroll
            for (int h = 0; h < 2; h++) {
                const int row = m0 + wm + mt * 16 + (lane >> 2) + h * 8;
                float v[16];
                #pragma unroll
                for (int nt = 0; nt < 8; nt++) {
                    v[2 * nt]     = acc[mt * 8 + nt][2 * h];
                    v[2 * nt + 1] = acc[mt * 8 + nt][2 * h + 1];
                }
                // two 32-col subtile reductions (v[0..7] and v[8..15])
                #pragma unroll
                for (int half = 0; half < 2; half++) {
                    float mx = v[half * 8];
                    #pragma unroll
                    for (int i = 1; i < 8; i++) mx = fmaxf(mx, v[half * 8 + i]);
                    mx = fmaxf(mx, __shfl_xor_sync(0xffffffffu, mx, 1));
                    mx = fmaxf(mx, __shfl_xor_sync(0xffffffffu, mx, 2));
                    float se = 0.0f;
                    #pragma unroll
                    for (int i = 0; i < 8; i++) se += expf(v[half * 8 + i] - mx);
                    se += __shfl_xor_sync(0xffffffffu, se, 1);
                    se += __shfl_xor_sync(0xffffffffu, se, 2);
                    if ((lane & 3) == 0)
                        g_part[prow0 + (size_t)row * 64 + subt0 + half] = make_float2(mx, se);
                }
                if (sband) {
                    const int cc = n0 + wn + (lane & 3) * 2;
                    float* sp = Sb + (size_t)row * N + cc;
                    #pragma unroll
                    for (int nt = 0; nt < 8; nt++)
                        *(float2*)(sp + nt * 8) = make_float2(v[2 * nt], v[2 * nt + 1]);
                }
            }
        }
    } else {
        // MODE 5: fused QKV projection
        const int seg = n0 >> 10;    // 0 = Q, 1 = K, 2 = V
        if (seg < 2) {
            __half* Co = seg ? g_Kh : g_Qh;
            const float LN1E4 = 9.210340371976184f;
            #pragma unroll
            for (int nt = 0; nt < 8; nt++) {
                const int cc = n0 + wn + nt * 8 + (lane & 3) * 2;
                const int ncol = cc & 1023;
                const int jj = ncol >> 1;
                float lgsv = logf((2.0f * (float)jj + 0.4f * 1024.0f) / (1.4f * 1024.0f));
                if (seg == 1) lgsv = -lgsv;
                const float invf = expf(-(float)jj * (2.0f / 1024.0f) * LN1E4);
                #pragma unroll
                for (int mt = 0; mt < 4; mt++) {
                    float* c = acc[mt * 8 + nt];
                    #pragma unroll
                    for (int h = 0; h < 2; h++) {
                        const int row = m0 + wm + mt * 16 + (lane >> 2) + h * 8;
                        const int l = row & (LL - 1);
                        const float lf = (float)l;
                        float scale = expf(lf * (1.0f / 512.0f) * lgsv);
                        float s, co;
                        sincos_red(lf * invf, &s, &co);
                        s *= scale; co *= scale;
                        float xe = c[2 * h], xo = c[2 * h + 1];
                        *(__half2*)(Co + (size_t)row * DH + ncol) =
                            __halves2half2(__float2half_rn(xe * co - xo * s),
                                           __float2half_rn(xo * co + xe * s));
                    }
                }
            }
        } else {
            #pragma unroll
            for (int mt = 0; mt < 4; mt++) {
                const int m = m0 + wm + mt * 16 + (lane >> 2);
                const int b = m >> 11;
                const int l = m & (LL - 1);
                __half* base = g_Vth + (size_t)b * DH * LL;
                #pragma unroll
                for (int nt = 0; nt < 8; nt++) {
                    const int cc = n0 + wn + nt * 8 + (lane & 3) * 2;
                    const int dh = cc - 2048;
                    float* c = acc[mt * 8 + nt];
                    base[(size_t)dh * LL + l]           = __float2half_rn(c[0]);
                    base[(size_t)(dh + 1) * LL + l]     = __float2half_rn(c[1]);
                    base[(size_t)dh * LL + l + 8]       = __float2half_rn(c[2]);
                    base[(size_t)(dh + 1) * LL + l + 8] = __float2half_rn(c[3]);
                }
            }
        }
    }
}

// ======================= X round (fp32 -> fp16) =======================
__global__ void round_x(const float* __restrict__ in, __half* __restrict__ oh, int n4)
{
    int i = blockIdx.x * blockDim.x + threadIdx.x;
    if (i >= n4) return;
    float4 v = ((const float4*)in)[i];
    ((__half2*)oh)[2 * i]     = __floats2half2_rn(v.x, v.y);
    ((__half2*)oh)[2 * i + 1] = __floats2half2_rn(v.z, v.w);
}

// ======================= weight transpose + fp16 round =======================
__global__ void transpose_h(const float* __restrict__ in, __half* __restrict__ out) {
    __shared__ float t[32][33];
    const int bx = blockIdx.x * 32, by = blockIdx.y * 32;
    #pragma unroll
    for (int i = threadIdx.y; i < 32; i += 8)
        t[i][threadIdx.x] = in[(size_t)(by + i) * DH + bx + threadIdx.x];
    __syncthreads();
    #pragma unroll
    for (int i = threadIdx.y; i < 32; i += 8)
        out[(size_t)(bx + i) * HH + by + threadIdx.x] =
            __float2half_rn(t[threadIdx.x][i]);
}

// ======================= combine partials + banded P production =======================
__global__ void __launch_bounds__(128, 8)
pk_kernel(const float* __restrict__ S, const float2* __restrict__ part,
          __half* __restrict__ Ph)
{
    const int q = blockIdx.x;
    const int b = blockIdx.y;
    const size_t rbase = (size_t)(b * LL + q);
    const float2* pp = part + rbase * 64;
    const int tid = threadIdx.x;
    const int lane = tid & 31;
    const int warp = tid >> 5;
    const float LN_GAMMA = -0.10536051565782628f;

    __shared__ float redm[4], redz[4];

    float2 pv = (tid < 64) ? pp[tid] : make_float2(-1e30f, 0.0f);
    float m = pv.x;
    #pragma unroll
    for (int o = 16; o > 0; o >>= 1)
        m = fmaxf(m, __shfl_xor_sync(0xffffffffu, m, o));
    if (lane == 0) redm[warp] = m;
    __syncthreads();
    m = fmaxf(fmaxf(redm[0], redm[1]), fmaxf(redm[2], redm[3]));

    float z = pv.y * expf(pv.x - m);
    #pragma unroll
    for (int o = 16; o > 0; o >>= 1)
        z += __shfl_xor_sync(0xffffffffu, z, o);
    if (lane == 0) redz[warp] = z;
    __syncthreads();
    const float invZ = 1.0f / (redz[0] + redz[1] + redz[2] + redz[3]);

    // union band for the 256-row group (matches MODE 6 S writes and MODE 7 reads)
    const int g = q >> 8;
    const int klo = max(0, 2 * g - BAND_T) * 128;
    const int khi = min(16, 2 * g + 2 + BAND_T) * 128;
    const float* Sr = S + rbase * LL;
    __half* Pr = Ph + rbase * LL;
    for (int k = klo + tid; k < khi; k += 128) {
        float d = expf(fabsf((float)(q - k)) * LN_GAMMA);
        Pr[k] = __float2half_rn(expf(Sr[k] - m) * d * invZ);
    }
}

// ======================= launcher =======================
extern "C" void kernel_launch(void* const* d_in, const int* in_sizes, int n_in,
                              void* d_out, int out_size)
{
    const float* X  = (const float*)d_in[0];
    const float* WQ = (const float*)d_in[1];
    const float* WK = (const float*)d_in[2];
    const float* WV = (const float*)d_in[3];
    float* out = (float*)d_out;

    __half *Xh, *Wt, *Qh, *Kh, *Vth, *Ph;
    float* S;
    float2* Pt;
    cudaGetSymbolAddress((void**)&Xh,  g_Xh);
    cudaGetSymbolAddress((void**)&Wt,  g_Wt);
    cudaGetSymbolAddress((void**)&Qh,  g_Qh);
    cudaGetSymbolAddress((void**)&Kh,  g_Kh);
    cudaGetSymbolAddress((void**)&Vth, g_Vth);
    cudaGetSymbolAddress((void**)&S,   g_S);
    cudaGetSymbolAddress((void**)&Ph,  g_Ph);
    cudaGetSymbolAddress((void**)&Pt,  g_part);

    cudaFuncSetAttribute(tgemm<5>, cudaFuncAttributeMaxDynamicSharedMemorySize, SMEM_TOTAL);
    cudaFuncSetAttribute(tgemm<6>, cudaFuncAttributeMaxDynamicSharedMemorySize, SMEM_TOTAL);
    cudaFuncSetAttribute(tgemm<7>, cudaFuncAttributeMaxDynamicSharedMemorySize, SMEM_TOTAL);

    const int M = BB * LL;  // 16384

    // 0) operand preparation
    int n4 = M * HH / 4;
    round_x<<<(n4 + 255) / 256, 256>>>(X, Xh, n4);
    dim3 tb(32, 8), tg(32, 32);
    transpose_h<<<tg, tb>>>(WQ, Wt);
    transpose_h<<<tg, tb>>>(WK, Wt + (size_t)HH * DH);
    transpose_h<<<tg, tb>>>(WV, Wt + (size_t)2 * HH * DH);

    // 1) fused QKV projection
    dim3 g1(3 * DH / 128, M / 256, 1);
    tgemm<5><<<g1, TGN, SMEM_TOTAL>>>(Xh, Wt, nullptr, M, 3 * DH, HH, 0, 0, 0);

    // 2) scores = Q K^T per batch -> banded S + softmax partials
    dim3 g2(LL / 128, LL / 256, BB);
    tgemm<6><<<g2, TGN, SMEM_TOTAL>>>(Qh, Kh, S, LL, LL, DH,
                                      (long long)LL * DH, (long long)LL * DH,
                                      (long long)LL * LL);

    // 3) combine partials + banded P = softmax * D (fp16)
    pk_kernel<<<dim3(LL, BB), 128>>>(S, Pt, Ph);

    // 4) out = P V per batch, banded k-loop
    dim3 g4(DH / 128, LL / 256, BB);
    tgemm<7><<<g4, TGN, SMEM_TOTAL>>>(Ph, Vth, out, LL, DH, LL,
                                      (long long)LL * LL, (long long)DH * LL,
                                      (long long)LL * DH);
}

// round 8
// speedup vs baseline: 8.4354x; 1.0554x over previous
#include <cuda_runtime.h>
#include <cuda_fp16.h>
#include <math.h>
#include <stdint.h>

// Problem constants (fixed by setup_inputs)
#define BB  8
#define LL  2048
#define HH  1024
#define DH  1024

#define TGN 512          // 16 warps per CTA (4 per SMSP)
#define STAGES 4
#define OFF_B   32768    // A tile 256x64 fp16 = 32KB
#define STAGE_BYTES 49152
#define SMEM_TOTAL (STAGES * STAGE_BYTES)   // 192 KB

#define BAND_T 2         // band half-width in 128-tiles (cutoff ~gamma^257)

// ---- scratch (static device globals; allocation-free) ----
__device__ __half g_Xh [(size_t)BB * LL * HH];
__device__ __half g_Wt [(size_t)3 * HH * DH];   // WQ^T | WK^T | WV^T
__device__ __half g_Qh [(size_t)BB * LL * DH];
__device__ __half g_Kh [(size_t)BB * LL * DH];
__device__ __half g_Vth[(size_t)BB * LL * DH];  // V^T per batch: [Dh][L]
__device__ float  g_S  [(size_t)BB * LL * LL];  // banded use only
__device__ __half g_Ph [(size_t)BB * LL * LL];  // banded use only
__device__ float2 g_part[(size_t)BB * LL * 64]; // per-row per-32col (max, sumexp)

// ======================= helpers =======================
__device__ __forceinline__ uint32_t smem_u32(const void* p) {
    uint32_t a;
    asm("{ .reg .u64 t; cvta.to.shared.u64 t, %1; cvt.u32.u64 %0, t; }" : "=r"(a) : "l"(p));
    return a;
}
__device__ __forceinline__ uint32_t sw128(uint32_t off) {
    return off ^ ((off >> 3) & 0x70);
}
__device__ __forceinline__ void cpa16(uint32_t dst, const void* src) {
    asm volatile("cp.async.cg.shared.global [%0], [%1], 16;" :: "r"(dst), "l"(src));
}
__device__ __forceinline__ void cp_commit() {
    asm volatile("cp.async.commit_group;" ::: "memory");
}
template<int N> __device__ __forceinline__ void cp_wait() {
    asm volatile("cp.async.wait_group %0;" :: "n"(N) : "memory");
}
__device__ __forceinline__ void ldsm_x4(uint32_t* r, uint32_t addr) {
    asm volatile("ldmatrix.sync.aligned.m8n8.x4.shared.b16 {%0,%1,%2,%3}, [%4];"
                 : "=r"(r[0]), "=r"(r[1]), "=r"(r[2]), "=r"(r[3]) : "r"(addr));
}
__device__ __forceinline__ void mma_f16(float* c, const uint32_t* a,
                                        uint32_t b0, uint32_t b1) {
    asm volatile(
        "mma.sync.aligned.m16n8k16.row.col.f32.f16.f16.f32 "
        "{%0,%1,%2,%3}, {%4,%5,%6,%7}, {%8,%9}, {%0,%1,%2,%3};"
        : "+f"(c[0]), "+f"(c[1]), "+f"(c[2]), "+f"(c[3])
        : "r"(a[0]), "r"(a[1]), "r"(a[2]), "r"(a[3]), "r"(b0), "r"(b1));
}

// Cody-Waite reduced sincos (survives --use_fast_math; theta in [0, ~2100))
__device__ __forceinline__ void sincos_red(float theta, float* s, float* c) {
    const float INV_2PI = 0.15915494309189535f;
    const float PI2_HI  = 6.28318548202514648f;
    const float PI2_LO  = -1.7484555e-7f;
    float k = nearbyintf(theta * INV_2PI);
    float r = __fmaf_rn(-k, PI2_HI, theta);
    r = __fmaf_rn(-k, PI2_LO, r);
    sincosf(r, s, c);
}

// ======================= mma.sync fp16 GEMM, 256x128 CTA tile, 16 warps =======================
// C[M,N] = A[M,K] * B[N,K]^T ; both fp16. Warp layout 4m x 4n, warptile 64x32.
// MODE 5: fused QKV projection epilogue (Q XPOS / K XPOS-inv / V^T)
// MODE 6: scores -> banded S + per-subtile (max, sumexp) partials
// MODE 7: banded P*V -> fp32 out
template<int MODE>
__global__ void __launch_bounds__(TGN, 1)
tgemm(const __half* __restrict__ Ah, const __half* __restrict__ Bh,
      float* __restrict__ Cf,
      int M, int N, int K,
      long long sA, long long sB, long long sC)
{
    extern __shared__ char smem[];
    const uint32_t sb = smem_u32(smem);
    const int tid  = threadIdx.x;
    const int wid  = tid >> 5;
    const int lane = tid & 31;

    Ah += (long long)blockIdx.z * sA;
    Bh += (long long)blockIdx.z * sB;
    const int m0 = blockIdx.y * 256;
    const int n0 = blockIdx.x * 128;

    // warp layout: 4 (m) x 4 (n); warp tile 64(m) x 32(n)
    const int wm = (wid & 3) * 64;
    const int wn = (wid >> 2) * 32;

    float acc[16][4];
    #pragma unroll
    for (int i = 0; i < 16; i++)
        #pragma unroll
        for (int j = 0; j < 4; j++) acc[i][j] = 0.0f;

    const int rowA = wm + (lane & 15);
    const int chA  = lane >> 4;
    const int rowB = wn + (lane & 7) + ((lane & 16) >> 1);
    const int chB  = (lane >> 3) & 1;

    // k64-tile range (banded for MODE 7)
    int ktlo = 0, k64n = K >> 6;
    if (MODE == 7) {
        const int g = (int)blockIdx.y;          // 256-row group
        const int t0 = max(0, 2 * g - BAND_T);
        const int t1 = min(K >> 7, 2 * g + 2 + BAND_T);
        ktlo = t0 << 1;
        k64n = (t1 - t0) << 1;                  // 8..12
    }

    const int cr  = tid >> 3;       // 0..63
    const int cch = tid & 7;

    auto issue = [&](int kt, int stg) {
        const uint32_t sbase = sb + (uint32_t)stg * STAGE_BYTES;
        #pragma unroll
        for (int p = 0; p < 4; p++) {           // A: 256 rows
            int r = cr + p * 64;
            uint32_t d = sw128((uint32_t)(r * 128 + cch * 16));
            cpa16(sbase + d, Ah + (size_t)(m0 + r) * K + kt * 64 + cch * 8);
        }
        #pragma unroll
        for (int p = 0; p < 2; p++) {           // B: 128 rows
            int r = cr + p * 64;
            uint32_t d = sw128((uint32_t)(r * 128 + cch * 16));
            cpa16(sbase + OFF_B + d, Bh + (size_t)(n0 + r) * K + kt * 64 + cch * 8);
        }
        cp_commit();
    };

    issue(ktlo, 0); issue(ktlo + 1, 1); issue(ktlo + 2, 2);

    for (int it = 0; it < k64n; ++it) {
        cp_wait<2>();
        __syncthreads();

        if (it + 3 < k64n) issue(ktlo + it + 3, (it + 3) & 3);
        else cp_commit();

        const uint32_t abase = sb + (uint32_t)((it & 3) * STAGE_BYTES);

        #pragma unroll
        for (int ks = 0; ks < 4; ks++) {
            uint32_t Af[16], Bf[8];
            #pragma unroll
            for (int mt = 0; mt < 4; mt++) {
                uint32_t off = sw128((uint32_t)((rowA + mt * 16) * 128 + ks * 32 + chA * 16));
                ldsm_x4(Af + mt * 4, abase + off);
            }
            #pragma unroll
            for (int pr = 0; pr < 2; pr++) {
                uint32_t off = sw128((uint32_t)((rowB + pr * 16) * 128 + ks * 32 + chB * 16));
                ldsm_x4(Bf + pr * 4, abase + OFF_B + off);
            }
            #pragma unroll
            for (int mt = 0; mt < 4; mt++)
                #pragma unroll
                for (int nt = 0; nt < 4; nt++) {
                    const int bi = (nt >> 1) * 4 + (nt & 1) * 2;
                    mma_f16(acc[mt * 4 + nt], Af + mt * 4, Bf[bi], Bf[bi + 1]);
                }
        }
    }

    // ======================= epilogue =======================
    if (MODE == 7) {
        float* Cb = Cf + (long long)blockIdx.z * sC;
        #pragma unroll
        for (int mt = 0; mt < 4; mt++) {
            const int r = m0 + wm + mt * 16 + (lane >> 2);
            #pragma unroll
            for (int nt = 0; nt < 4; nt++) {
                const int cc = n0 + wn + nt * 8 + (lane & 3) * 2;
                float* c = acc[mt * 4 + nt];
                *(float2*)(Cb + (size_t)r * N + cc)       = make_float2(c[0], c[1]);
                *(float2*)(Cb + (size_t)(r + 8) * N + cc) = make_float2(c[2], c[3]);
            }
        }
    } else if (MODE == 6) {
        const int g  = m0 >> 8;                 // 256-row group
        const int kt = n0 >> 7;
        const bool sband = (kt >= 2 * g - BAND_T) && (kt < 2 * g + 2 + BAND_T);
        float* Sb = Cf + (long long)blockIdx.z * sC;
        const size_t prow0 = (size_t)(blockIdx.z * LL) * 64;
        const int subt = (n0 + wn) >> 5;        // this warp's 32-col subtile
        #pragma unroll
        for (int mt = 0; mt < 4; mt++) {
            #pragma unroll
            for (int h = 0; h < 2; h++) {
                const int row = m0 + wm + mt * 16 + (lane >> 2) + h * 8;
                float v[8];
                #pragma unroll
                for (int nt = 0; nt < 4; nt++) {
                    v[2 * nt]     = acc[mt * 4 + nt][2 * h];
                    v[2 * nt + 1] = acc[mt * 4 + nt][2 * h + 1];
                }
                float mx = v[0];
                #pragma unroll
                for (int i = 1; i < 8; i++) mx = fmaxf(mx, v[i]);
                mx = fmaxf(mx, __shfl_xor_sync(0xffffffffu, mx, 1));
                mx = fmaxf(mx, __shfl_xor_sync(0xffffffffu, mx, 2));
                float se = 0.0f;
                #pragma unroll
                for (int i = 0; i < 8; i++) se += expf(v[i] - mx);
                se += __shfl_xor_sync(0xffffffffu, se, 1);
                se += __shfl_xor_sync(0xffffffffu, se, 2);
                if ((lane & 3) == 0)
                    g_part[prow0 + (size_t)row * 64 + subt] = make_float2(mx, se);
                if (sband) {
                    const int cc = n0 + wn + (lane & 3) * 2;
                    float* sp = Sb + (size_t)row * N + cc;
                    #pragma unroll
                    for (int nt = 0; nt < 4; nt++)
                        *(float2*)(sp + nt * 8) = make_float2(v[2 * nt], v[2 * nt + 1]);
                }
            }
        }
    } else {
        // MODE 5: fused QKV projection
        const int seg = n0 >> 10;    // 0 = Q, 1 = K, 2 = V  (CTA never crosses segs)
        if (seg < 2) {
            __half* Co = seg ? g_Kh : g_Qh;
            const float LN1E4 = 9.210340371976184f;
            #pragma unroll
            for (int nt = 0; nt < 4; nt++) {
                const int cc = n0 + wn + nt * 8 + (lane & 3) * 2;
                const int ncol = cc & 1023;
                const int jj = ncol >> 1;
                float lgsv = logf((2.0f * (float)jj + 0.4f * 1024.0f) / (1.4f * 1024.0f));
                if (seg == 1) lgsv = -lgsv;
                const float invf = expf(-(float)jj * (2.0f / 1024.0f) * LN1E4);
                #pragma unroll
                for (int mt = 0; mt < 4; mt++) {
                    float* c = acc[mt * 4 + nt];
                    #pragma unroll
                    for (int h = 0; h < 2; h++) {
                        const int row = m0 + wm + mt * 16 + (lane >> 2) + h * 8;
                        const int l = row & (LL - 1);
                        const float lf = (float)l;
                        float scale = expf(lf * (1.0f / 512.0f) * lgsv);
                        float s, co;
                        sincos_red(lf * invf, &s, &co);
                        s *= scale; co *= scale;
                        float xe = c[2 * h], xo = c[2 * h + 1];
                        *(__half2*)(Co + (size_t)row * DH + ncol) =
                            __halves2half2(__float2half_rn(xe * co - xo * s),
                                           __float2half_rn(xo * co + xe * s));
                    }
                }
            }
        } else {
            #pragma unroll
            for (int mt = 0; mt < 4; mt++) {
                const int m = m0 + wm + mt * 16 + (lane >> 2);
                const int b = m >> 11;
                const int l = m & (LL - 1);
                __half* base = g_Vth + (size_t)b * DH * LL;
                #pragma unroll
                for (int nt = 0; nt < 4; nt++) {
                    const int cc = n0 + wn + nt * 8 + (lane & 3) * 2;
                    const int dh = cc - 2048;
                    float* c = acc[mt * 4 + nt];
                    base[(size_t)dh * LL + l]           = __float2half_rn(c[0]);
                    base[(size_t)(dh + 1) * LL + l]     = __float2half_rn(c[1]);
                    base[(size_t)dh * LL + l + 8]       = __float2half_rn(c[2]);
                    base[(size_t)(dh + 1) * LL + l + 8] = __float2half_rn(c[3]);
                }
            }
        }
    }
}

// ======================= X round (fp32 -> fp16) =======================
__global__ void round_x(const float* __restrict__ in, __half* __restrict__ oh, int n4)
{
    int i = blockIdx.x * blockDim.x + threadIdx.x;
    if (i >= n4) return;
    float4 v = ((const float4*)in)[i];
    ((__half2*)oh)[2 * i]     = __floats2half2_rn(v.x, v.y);
    ((__half2*)oh)[2 * i + 1] = __floats2half2_rn(v.z, v.w);
}

// ======================= weight transpose + fp16 round =======================
__global__ void transpose_h(const float* __restrict__ in, __half* __restrict__ out) {
    __shared__ float t[32][33];
    const int bx = blockIdx.x * 32, by = blockIdx.y * 32;
    #pragma unroll
    for (int i = threadIdx.y; i < 32; i += 8)
        t[i][threadIdx.x] = in[(size_t)(by + i) * DH + bx + threadIdx.x];
    __syncthreads();
    #pragma unroll
    for (int i = threadIdx.y; i < 32; i += 8)
        out[(size_t)(bx + i) * HH + by + threadIdx.x] =
            __float2half_rn(t[threadIdx.x][i]);
}

// ======================= combine partials + banded P production =======================
__global__ void __launch_bounds__(128, 8)
pk_kernel(const float* __restrict__ S, const float2* __restrict__ part,
          __half* __restrict__ Ph)
{
    const int q = blockIdx.x;
    const int b = blockIdx.y;
    const size_t rbase = (size_t)(b * LL + q);
    const float2* pp = part + rbase * 64;
    const int tid = threadIdx.x;
    const int lane = tid & 31;
    const int warp = tid >> 5;
    const float LN_GAMMA = -0.10536051565782628f;

    __shared__ float redm[4], redz[4];

    float2 pv = (tid < 64) ? pp[tid] : make_float2(-1e30f, 0.0f);
    float m = pv.x;
    #pragma unroll
    for (int o = 16; o > 0; o >>= 1)
        m = fmaxf(m, __shfl_xor_sync(0xffffffffu, m, o));
    if (lane == 0) redm[warp] = m;
    __syncthreads();
    m = fmaxf(fmaxf(redm[0], redm[1]), fmaxf(redm[2], redm[3]));

    float z = pv.y * expf(pv.x - m);
    #pragma unroll
    for (int o = 16; o > 0; o >>= 1)
        z += __shfl_xor_sync(0xffffffffu, z, o);
    if (lane == 0) redz[warp] = z;
    __syncthreads();
    const float invZ = 1.0f / (redz[0] + redz[1] + redz[2] + redz[3]);

    // union band for the 256-row group (matches MODE 6 S writes and MODE 7 reads)
    const int g = q >> 8;
    const int klo = max(0, 2 * g - BAND_T) * 128;
    const int khi = min(16, 2 * g + 2 + BAND_T) * 128;
    const float* Sr = S + rbase * LL;
    __half* Pr = Ph + rbase * LL;
    for (int k = klo + tid; k < khi; k += 128) {
        float d = expf(fabsf((float)(q - k)) * LN_GAMMA);
        Pr[k] = __float2half_rn(expf(Sr[k] - m) * d * invZ);
    }
}

// ======================= launcher =======================
extern "C" void kernel_launch(void* const* d_in, const int* in_sizes, int n_in,
                              void* d_out, int out_size)
{
    const float* X  = (const float*)d_in[0];
    const float* WQ = (const float*)d_in[1];
    const float* WK = (const float*)d_in[2];
    const float* WV = (const float*)d_in[3];
    float* out = (float*)d_out;

    __half *Xh, *Wt, *Qh, *Kh, *Vth, *Ph;
    float* S;
    float2* Pt;
    cudaGetSymbolAddress((void**)&Xh,  g_Xh);
    cudaGetSymbolAddress((void**)&Wt,  g_Wt);
    cudaGetSymbolAddress((void**)&Qh,  g_Qh);
    cudaGetSymbolAddress((void**)&Kh,  g_Kh);
    cudaGetSymbolAddress((void**)&Vth, g_Vth);
    cudaGetSymbolAddress((void**)&S,   g_S);
    cudaGetSymbolAddress((void**)&Ph,  g_Ph);
    cudaGetSymbolAddress((void**)&Pt,  g_part);

    cudaFuncSetAttribute(tgemm<5>, cudaFuncAttributeMaxDynamicSharedMemorySize, SMEM_TOTAL);
    cudaFuncSetAttribute(tgemm<6>, cudaFuncAttributeMaxDynamicSharedMemorySize, SMEM_TOTAL);
    cudaFuncSetAttribute(tgemm<7>, cudaFuncAttributeMaxDynamicSharedMemorySize, SMEM_TOTAL);

    const int M = BB * LL;  // 16384

    // 0) operand preparation
    int n4 = M * HH / 4;
    round_x<<<(n4 + 255) / 256, 256>>>(X, Xh, n4);
    dim3 tb(32, 8), tg(32, 32);
    transpose_h<<<tg, tb>>>(WQ, Wt);
    transpose_h<<<tg, tb>>>(WK, Wt + (size_t)HH * DH);
    transpose_h<<<tg, tb>>>(WV, Wt + (size_t)2 * HH * DH);

    // 1) fused QKV projection
    dim3 g1(3 * DH / 128, M / 256, 1);
    tgemm<5><<<g1, TGN, SMEM_TOTAL>>>(Xh, Wt, nullptr, M, 3 * DH, HH, 0, 0, 0);

    // 2) scores = Q K^T per batch -> banded S + softmax partials
    dim3 g2(LL / 128, LL / 256, BB);
    tgemm<6><<<g2, TGN, SMEM_TOTAL>>>(Qh, Kh, S, LL, LL, DH,
                                      (long long)LL * DH, (long long)LL * DH,
                                      (long long)LL * LL);

    // 3) combine partials + banded P = softmax * D (fp16)
    pk_kernel<<<dim3(LL, BB), 128>>>(S, Pt, Ph);

    // 4) out = P V per batch, banded k-loop
    dim3 g4(DH / 128, LL / 256, BB);
    tgemm<7><<<g4, TGN, SMEM_TOTAL>>>(Ph, Vth, out, LL, DH, LL,
                                      (long long)LL * LL, (long long)DH * LL,
                                      (long long)LL * DH);
}

// round 9
// speedup vs baseline: 9.2618x; 1.0980x over previous
#include <cuda_runtime.h>
#include <cuda_fp16.h>
#include <math.h>
#include <stdint.h>

// Problem constants (fixed by setup_inputs)
#define BB  8
#define LL  2048
#define HH  1024
#define DH  1024

#define TGN 256          // 8 warps per CTA, 2 CTAs per SM
#define STAGES 3
#define OFF_B   16384    // A tile 128x64 fp16 = 16KB
#define STAGE_BYTES 32768
#define SMEM_TOTAL (STAGES * STAGE_BYTES)   // 96 KB -> 2 CTAs/SM

// band half-width = 1 tile of 128 (cutoff gamma^129 ~ 1.2e-6; rel contribution ~6e-7)

// ---- scratch (static device globals; allocation-free) ----
__device__ __half g_Xh [(size_t)BB * LL * HH];
__device__ __half g_Wt [(size_t)3 * HH * DH];   // WQ^T | WK^T | WV^T
__device__ __half g_Qh [(size_t)BB * LL * DH];
__device__ __half g_Kh [(size_t)BB * LL * DH];
__device__ __half g_Vth[(size_t)BB * LL * DH];  // V^T per batch: [Dh][L]
__device__ float  g_S  [(size_t)BB * LL * LL];  // banded use only
__device__ __half g_Ph [(size_t)BB * LL * LL];  // banded use only
__device__ float2 g_part[(size_t)BB * LL * 64]; // per-row per-32col (max, sumexp)

// ======================= helpers =======================
__device__ __forceinline__ uint32_t smem_u32(const void* p) {
    uint32_t a;
    asm("{ .reg .u64 t; cvta.to.shared.u64 t, %1; cvt.u32.u64 %0, t; }" : "=r"(a) : "l"(p));
    return a;
}
__device__ __forceinline__ uint32_t sw128(uint32_t off) {
    return off ^ ((off >> 3) & 0x70);
}
__device__ __forceinline__ void cpa16(uint32_t dst, const void* src) {
    asm volatile("cp.async.cg.shared.global [%0], [%1], 16;" :: "r"(dst), "l"(src));
}
__device__ __forceinline__ void cp_commit() {
    asm volatile("cp.async.commit_group;" ::: "memory");
}
template<int N> __device__ __forceinline__ void cp_wait() {
    asm volatile("cp.async.wait_group %0;" :: "n"(N) : "memory");
}
__device__ __forceinline__ void ldsm_x4(uint32_t* r, uint32_t addr) {
    asm volatile("ldmatrix.sync.aligned.m8n8.x4.shared.b16 {%0,%1,%2,%3}, [%4];"
                 : "=r"(r[0]), "=r"(r[1]), "=r"(r[2]), "=r"(r[3]) : "r"(addr));
}
__device__ __forceinline__ void mma_f16(float* c, const uint32_t* a,
                                        uint32_t b0, uint32_t b1) {
    asm volatile(
        "mma.sync.aligned.m16n8k16.row.col.f32.f16.f16.f32 "
        "{%0,%1,%2,%3}, {%4,%5,%6,%7}, {%8,%9}, {%0,%1,%2,%3};"
        : "+f"(c[0]), "+f"(c[1]), "+f"(c[2]), "+f"(c[3])
        : "r"(a[0]), "r"(a[1]), "r"(a[2]), "r"(a[3]), "r"(b0), "r"(b1));
}

// Cody-Waite reduced sincos (survives --use_fast_math; theta in [0, ~2100))
__device__ __forceinline__ void sincos_red(float theta, float* s, float* c) {
    const float INV_2PI = 0.15915494309189535f;
    const float PI2_HI  = 6.28318548202514648f;
    const float PI2_LO  = -1.7484555e-7f;
    float k = nearbyintf(theta * INV_2PI);
    float r = __fmaf_rn(-k, PI2_HI, theta);
    r = __fmaf_rn(-k, PI2_LO, r);
    sincosf(r, s, c);
}

// ======================= mma.sync fp16 GEMM, 128x128 CTA tile, 2 CTAs/SM =======================
// C[M,N] = A[M,K] * B[N,K]^T ; both fp16. Warp layout 2m x 4n, warptile 64x32.
// MODE 5: fused QKV projection epilogue (Q XPOS / K XPOS-inv / V^T)
// MODE 6: scores -> banded S + per-subtile (max, sumexp) partials
// MODE 7: banded P*V -> fp32 out
template<int MODE>
__global__ void __launch_bounds__(TGN, 2)
tgemm(const __half* __restrict__ Ah, const __half* __restrict__ Bh,
      float* __restrict__ Cf,
      int M, int N, int K,
      long long sA, long long sB, long long sC)
{
    extern __shared__ char smem[];
    const uint32_t sb = smem_u32(smem);
    const int tid  = threadIdx.x;
    const int wid  = tid >> 5;
    const int lane = tid & 31;

    Ah += (long long)blockIdx.z * sA;
    Bh += (long long)blockIdx.z * sB;
    const int m0 = blockIdx.y * 128;
    const int n0 = blockIdx.x * 128;

    // warp layout: 2 (m) x 4 (n); warp tile 64(m) x 32(n)
    const int wm = (wid & 1) * 64;
    const int wn = (wid >> 1) * 32;

    float acc[16][4];
    #pragma unroll
    for (int i = 0; i < 16; i++)
        #pragma unroll
        for (int j = 0; j < 4; j++) acc[i][j] = 0.0f;

    const int rowA = wm + (lane & 15);
    const int chA  = lane >> 4;
    const int rowB = wn + (lane & 7) + ((lane & 16) >> 1);
    const int chB  = (lane >> 3) & 1;

    // k64-tile range (banded for MODE 7)
    int ktlo = 0, k64n = K >> 6;
    if (MODE == 7) {
        const int qt = (int)blockIdx.y;         // 128-row tile index
        const int t0 = max(0, qt - 1);
        const int t1 = min(K >> 7, qt + 2);
        ktlo = t0 << 1;
        k64n = (t1 - t0) << 1;                  // 4 or 6
    }

    const int cr  = tid >> 3;       // 0..31
    const int cch = tid & 7;

    auto issue = [&](int kt, int stg) {
        const uint32_t sbase = sb + (uint32_t)stg * STAGE_BYTES;
        #pragma unroll
        for (int p = 0; p < 4; p++) {           // A: 128 rows
            int r = cr + p * 32;
            uint32_t d = sw128((uint32_t)(r * 128 + cch * 16));
            cpa16(sbase + d, Ah + (size_t)(m0 + r) * K + kt * 64 + cch * 8);
        }
        #pragma unroll
        for (int p = 0; p < 4; p++) {           // B: 128 rows
            int r = cr + p * 32;
            uint32_t d = sw128((uint32_t)(r * 128 + cch * 16));
            cpa16(sbase + OFF_B + d, Bh + (size_t)(n0 + r) * K + kt * 64 + cch * 8);
        }
        cp_commit();
    };

    issue(ktlo, 0); issue(ktlo + 1, 1);

    for (int it = 0; it < k64n; ++it) {
        cp_wait<1>();
        __syncthreads();

        if (it + 2 < k64n) issue(ktlo + it + 2, (it + 2) % 3);
        else cp_commit();

        const uint32_t abase = sb + (uint32_t)((it % 3) * STAGE_BYTES);

        #pragma unroll
        for (int ks = 0; ks < 4; ks++) {
            uint32_t Af[16], Bf[8];
            #pragma unroll
            for (int mt = 0; mt < 4; mt++) {
                uint32_t off = sw128((uint32_t)((rowA + mt * 16) * 128 + ks * 32 + chA * 16));
                ldsm_x4(Af + mt * 4, abase + off);
            }
            #pragma unroll
            for (int pr = 0; pr < 2; pr++) {
                uint32_t off = sw128((uint32_t)((rowB + pr * 16) * 128 + ks * 32 + chB * 16));
                ldsm_x4(Bf + pr * 4, abase + OFF_B + off);
            }
            #pragma unroll
            for (int mt = 0; mt < 4; mt++)
                #pragma unroll
                for (int nt = 0; nt < 4; nt++) {
                    const int bi = (nt >> 1) * 4 + (nt & 1) * 2;
                    mma_f16(acc[mt * 4 + nt], Af + mt * 4, Bf[bi], Bf[bi + 1]);
                }
        }
    }

    // ======================= epilogue =======================
    if (MODE == 7) {
        float* Cb = Cf + (long long)blockIdx.z * sC;
        #pragma unroll
        for (int mt = 0; mt < 4; mt++) {
            const int r = m0 + wm + mt * 16 + (lane >> 2);
            #pragma unroll
            for (int nt = 0; nt < 4; nt++) {
                const int cc = n0 + wn + nt * 8 + (lane & 3) * 2;
                float* c = acc[mt * 4 + nt];
                *(float2*)(Cb + (size_t)r * N + cc)       = make_float2(c[0], c[1]);
                *(float2*)(Cb + (size_t)(r + 8) * N + cc) = make_float2(c[2], c[3]);
            }
        }
    } else if (MODE == 6) {
        const int qt = m0 >> 7;
        const int kt = n0 >> 7;
        const bool sband = (kt >= qt - 1) && (kt <= qt + 1);
        float* Sb = Cf + (long long)blockIdx.z * sC;
        const size_t prow0 = (size_t)(blockIdx.z * LL) * 64;
        const int subt = (n0 + wn) >> 5;        // this warp's 32-col subtile
        #pragma unroll
        for (int mt = 0; mt < 4; mt++) {
            #pragma unroll
            for (int h = 0; h < 2; h++) {
                const int row = m0 + wm + mt * 16 + (lane >> 2) + h * 8;
                float v[8];
                #pragma unroll
                for (int nt = 0; nt < 4; nt++) {
                    v[2 * nt]     = acc[mt * 4 + nt][2 * h];
                    v[2 * nt + 1] = acc[mt * 4 + nt][2 * h + 1];
                }
                float mx = v[0];
                #pragma unroll
                for (int i = 1; i < 8; i++) mx = fmaxf(mx, v[i]);
                mx = fmaxf(mx, __shfl_xor_sync(0xffffffffu, mx, 1));
                mx = fmaxf(mx, __shfl_xor_sync(0xffffffffu, mx, 2));
                float se = 0.0f;
                #pragma unroll
                for (int i = 0; i < 8; i++) se += expf(v[i] - mx);
                se += __shfl_xor_sync(0xffffffffu, se, 1);
                se += __shfl_xor_sync(0xffffffffu, se, 2);
                if ((lane & 3) == 0)
                    g_part[prow0 + (size_t)row * 64 + subt] = make_float2(mx, se);
                if (sband) {
                    const int cc = n0 + wn + (lane & 3) * 2;
                    float* sp = Sb + (size_t)row * N + cc;
                    #pragma unroll
                    for (int nt = 0; nt < 4; nt++)
                        *(float2*)(sp + nt * 8) = make_float2(v[2 * nt], v[2 * nt + 1]);
                }
            }
        }
    } else {
        // MODE 5: fused QKV projection
        const int seg = n0 >> 10;    // 0 = Q, 1 = K, 2 = V  (CTA never crosses segs)
        if (seg < 2) {
            __half* Co = seg ? g_Kh : g_Qh;
            const float LN1E4 = 9.210340371976184f;
            #pragma unroll
            for (int nt = 0; nt < 4; nt++) {
                const int cc = n0 + wn + nt * 8 + (lane & 3) * 2;
                const int ncol = cc & 1023;
                const int jj = ncol >> 1;
                float lgsv = logf((2.0f * (float)jj + 0.4f * 1024.0f) / (1.4f * 1024.0f));
                if (seg == 1) lgsv = -lgsv;
                const float invf = expf(-(float)jj * (2.0f / 1024.0f) * LN1E4);
                #pragma unroll
                for (int mt = 0; mt < 4; mt++) {
                    float* c = acc[mt * 4 + nt];
                    #pragma unroll
                    for (int h = 0; h < 2; h++) {
                        const int row = m0 + wm + mt * 16 + (lane >> 2) + h * 8;
                        const int l = row & (LL - 1);
                        const float lf = (float)l;
                        float scale = expf(lf * (1.0f / 512.0f) * lgsv);
                        float s, co;
                        sincos_red(lf * invf, &s, &co);
                        s *= scale; co *= scale;
                        float xe = c[2 * h], xo = c[2 * h + 1];
                        *(__half2*)(Co + (size_t)row * DH + ncol) =
                            __halves2half2(__float2half_rn(xe * co - xo * s),
                                           __float2half_rn(xo * co + xe * s));
                    }
                }
            }
        } else {
            #pragma unroll
            for (int mt = 0; mt < 4; mt++) {
                const int m = m0 + wm + mt * 16 + (lane >> 2);
                const int b = m >> 11;
                const int l = m & (LL - 1);
                __half* base = g_Vth + (size_t)b * DH * LL;
                #pragma unroll
                for (int nt = 0; nt < 4; nt++) {
                    const int cc = n0 + wn + nt * 8 + (lane & 3) * 2;
                    const int dh = cc - 2048;
                    float* c = acc[mt * 4 + nt];
                    base[(size_t)dh * LL + l]           = __float2half_rn(c[0]);
                    base[(size_t)(dh + 1) * LL + l]     = __float2half_rn(c[1]);
                    base[(size_t)dh * LL + l + 8]       = __float2half_rn(c[2]);
                    base[(size_t)(dh + 1) * LL + l + 8] = __float2half_rn(c[3]);
                }
            }
        }
    }
}

// ======================= X round (fp32 -> fp16) =======================
__global__ void round_x(const float* __restrict__ in, __half* __restrict__ oh, int n4)
{
    int i = blockIdx.x * blockDim.x + threadIdx.x;
    if (i >= n4) return;
    float4 v = ((const float4*)in)[i];
    ((__half2*)oh)[2 * i]     = __floats2half2_rn(v.x, v.y);
    ((__half2*)oh)[2 * i + 1] = __floats2half2_rn(v.z, v.w);
}

// ======================= weight transpose + fp16 round =======================
__global__ void transpose_h(const float* __restrict__ in, __half* __restrict__ out) {
    __shared__ float t[32][33];
    const int bx = blockIdx.x * 32, by = blockIdx.y * 32;
    #pragma unroll
    for (int i = threadIdx.y; i < 32; i += 8)
        t[i][threadIdx.x] = in[(size_t)(by + i) * DH + bx + threadIdx.x];
    __syncthreads();
    #pragma unroll
    for (int i = threadIdx.y; i < 32; i += 8)
        out[(size_t)(bx + i) * HH + by + threadIdx.x] =
            __float2half_rn(t[threadIdx.x][i]);
}

// ======================= combine partials + banded P production =======================
__global__ void __launch_bounds__(128, 8)
pk_kernel(const float* __restrict__ S, const float2* __restrict__ part,
          __half* __restrict__ Ph)
{
    const int q = blockIdx.x;
    const int b = blockIdx.y;
    const size_t rbase = (size_t)(b * LL + q);
    const float2* pp = part + rbase * 64;
    const int tid = threadIdx.x;
    const int lane = tid & 31;
    const int warp = tid >> 5;
    const float LN_GAMMA = -0.10536051565782628f;

    __shared__ float redm[4], redz[4];

    float2 pv = (tid < 64) ? pp[tid] : make_float2(-1e30f, 0.0f);
    float m = pv.x;
    #pragma unroll
    for (int o = 16; o > 0; o >>= 1)
        m = fmaxf(m, __shfl_xor_sync(0xffffffffu, m, o));
    if (lane == 0) redm[warp] = m;
    __syncthreads();
    m = fmaxf(fmaxf(redm[0], redm[1]), fmaxf(redm[2], redm[3]));

    float z = pv.y * expf(pv.x - m);
    #pragma unroll
    for (int o = 16; o > 0; o >>= 1)
        z += __shfl_xor_sync(0xffffffffu, z, o);
    if (lane == 0) redz[warp] = z;
    __syncthreads();
    const float invZ = 1.0f / (redz[0] + redz[1] + redz[2] + redz[3]);

    // band for the 128-row tile (matches MODE 6 S writes and MODE 7 reads)
    const int qt = q >> 7;
    const int klo = max(0, qt - 1) * 128;
    const int khi = min(16, qt + 2) * 128;
    const float* Sr = S + rbase * LL;
    __half* Pr = Ph + rbase * LL;
    for (int k = klo + tid; k < khi; k += 128) {
        float d = expf(fabsf((float)(q - k)) * LN_GAMMA);
        Pr[k] = __float2half_rn(expf(Sr[k] - m) * d * invZ);
    }
}

// ======================= launcher =======================
extern "C" void kernel_launch(void* const* d_in, const int* in_sizes, int n_in,
                              void* d_out, int out_size)
{
    const float* X  = (const float*)d_in[0];
    const float* WQ = (const float*)d_in[1];
    const float* WK = (const float*)d_in[2];
    const float* WV = (const float*)d_in[3];
    float* out = (float*)d_out;

    __half *Xh, *Wt, *Qh, *Kh, *Vth, *Ph;
    float* S;
    float2* Pt;
    cudaGetSymbolAddress((void**)&Xh,  g_Xh);
    cudaGetSymbolAddress((void**)&Wt,  g_Wt);
    cudaGetSymbolAddress((void**)&Qh,  g_Qh);
    cudaGetSymbolAddress((void**)&Kh,  g_Kh);
    cudaGetSymbolAddress((void**)&Vth, g_Vth);
    cudaGetSymbolAddress((void**)&S,   g_S);
    cudaGetSymbolAddress((void**)&Ph,  g_Ph);
    cudaGetSymbolAddress((void**)&Pt,  g_part);

    cudaFuncSetAttribute(tgemm<5>, cudaFuncAttributeMaxDynamicSharedMemorySize, SMEM_TOTAL);
    cudaFuncSetAttribute(tgemm<6>, cudaFuncAttributeMaxDynamicSharedMemorySize, SMEM_TOTAL);
    cudaFuncSetAttribute(tgemm<7>, cudaFuncAttributeMaxDynamicSharedMemorySize, SMEM_TOTAL);

    const int M = BB * LL;  // 16384

    // 0) operand preparation
    int n4 = M * HH / 4;
    round_x<<<(n4 + 255) / 256, 256>>>(X, Xh, n4);
    dim3 tb(32, 8), tg(32, 32);
    transpose_h<<<tg, tb>>>(WQ, Wt);
    transpose_h<<<tg, tb>>>(WK, Wt + (size_t)HH * DH);
    transpose_h<<<tg, tb>>>(WV, Wt + (size_t)2 * HH * DH);

    // 1) fused QKV projection
    dim3 g1(3 * DH / 128, M / 128, 1);
    tgemm<5><<<g1, TGN, SMEM_TOTAL>>>(Xh, Wt, nullptr, M, 3 * DH, HH, 0, 0, 0);

    // 2) scores = Q K^T per batch -> banded S + softmax partials
    dim3 g2(LL / 128, LL / 128, BB);
    tgemm<6><<<g2, TGN, SMEM_TOTAL>>>(Qh, Kh, S, LL, LL, DH,
                                      (long long)LL * DH, (long long)LL * DH,
                                      (long long)LL * LL);

    // 3) combine partials + banded P = softmax * D (fp16)
    pk_kernel<<<dim3(LL, BB), 128>>>(S, Pt, Ph);

    // 4) out = P V per batch, banded k-loop
    dim3 g4(DH / 128, LL / 128, BB);
    tgemm<7><<<g4, TGN, SMEM_TOTAL>>>(Ph, Vth, out, LL, DH, LL,
                                      (long long)LL * LL, (long long)DH * LL,
                                      (long long)LL * DH);
}